// round 8
// baseline (speedup 1.0000x reference)
#include <cuda_runtime.h>
#include <cuda_fp16.h>
#include <math.h>

// Problem constants
static const int BATCH  = 4;
static const int SEQ    = 2048;
static const int DIM    = 1024;
static const int NHEAD  = 16;
static const int HDIM   = 64;
static const int LATENT = 128;
static const int QRANK  = 256;
static const int MTOT   = BATCH * SEQ;          // 8192
static const int KVLD   = 2 * DIM;              // 2048

// Scratch (no allocations allowed) ------------------------------------------
__device__ float  g_kvlat[(size_t)MTOT * LATENT];
__device__ float  g_qlat [(size_t)MTOT * QRANK];
__device__ float  g_ctx  [(size_t)MTOT * DIM];
__device__ __half g_kv16 [(size_t)MTOT * 2 * DIM];   // K|V in fp16
__device__ __half g_q16  [(size_t)MTOT * DIM];       // Q in fp16

// ---------------------------------------------------------------------------
// helpers
// ---------------------------------------------------------------------------
__device__ __forceinline__ unsigned f2tf(float x) {
    unsigned u;
    asm("cvt.rna.tf32.f32 %0, %1;" : "=r"(u) : "f"(x));
    return u;
}

__device__ __forceinline__ void mma_tf32(float* d, const unsigned* a, const unsigned* b) {
    asm volatile(
        "mma.sync.aligned.m16n8k8.row.col.f32.tf32.tf32.f32 "
        "{%0,%1,%2,%3}, {%4,%5,%6,%7}, {%8,%9}, {%0,%1,%2,%3};"
        : "+f"(d[0]), "+f"(d[1]), "+f"(d[2]), "+f"(d[3])
        : "r"(a[0]), "r"(a[1]), "r"(a[2]), "r"(a[3]), "r"(b[0]), "r"(b[1]));
}

__device__ __forceinline__ void mma_f16(float* d, const unsigned* a, const unsigned* b) {
    asm volatile(
        "mma.sync.aligned.m16n8k16.row.col.f32.f16.f16.f32 "
        "{%0,%1,%2,%3}, {%4,%5,%6,%7}, {%8,%9}, {%0,%1,%2,%3};"
        : "+f"(d[0]), "+f"(d[1]), "+f"(d[2]), "+f"(d[3])
        : "r"(a[0]), "r"(a[1]), "r"(a[2]), "r"(a[3]), "r"(b[0]), "r"(b[1]));
}

__device__ __forceinline__ void ldm_x4(unsigned& r0, unsigned& r1, unsigned& r2, unsigned& r3,
                                       unsigned addr) {
    asm volatile("ldmatrix.sync.aligned.m8n8.x4.shared.b16 {%0,%1,%2,%3}, [%4];"
        : "=r"(r0), "=r"(r1), "=r"(r2), "=r"(r3) : "r"(addr));
}
__device__ __forceinline__ void ldm_x4t(unsigned& r0, unsigned& r1, unsigned& r2, unsigned& r3,
                                        unsigned addr) {
    asm volatile("ldmatrix.sync.aligned.m8n8.x4.trans.shared.b16 {%0,%1,%2,%3}, [%4];"
        : "=r"(r0), "=r"(r1), "=r"(r2), "=r"(r3) : "r"(addr));
}

__device__ __forceinline__ float ex2f(float x) {
    float y;
    asm("ex2.approx.f32 %0, %1;" : "=f"(y) : "f"(x));
    return y;
}

__device__ __forceinline__ void cpa16(void* smem, const void* g) {
    unsigned s = (unsigned)__cvta_generic_to_shared(smem);
    asm volatile("cp.async.cg.shared.global [%0], [%1], 16;" :: "r"(s), "l"(g));
}
__device__ __forceinline__ void cp_commit() { asm volatile("cp.async.commit_group;"); }
__device__ __forceinline__ void cp_wait1()  { asm volatile("cp.async.wait_group 1;"); }
__device__ __forceinline__ void cp_wait0()  { asm volatile("cp.async.wait_group 0;"); }

// ---------------------------------------------------------------------------
// tf32 GEMM: C[M,N] = A[M,K] @ W[K,N] + bias. BM=BN=128, BK=32, 256 threads.
// Optional fp32 (C) and/or fp16 (C16) outputs.
// ---------------------------------------------------------------------------
static const int GA_STRIDE = 128 * 36;
static const int GW_STRIDE = 32 * 136;
static const int GEMM_SMEM = (2 * GA_STRIDE + 2 * GW_STRIDE) * 4;  // 71680 B

__global__ __launch_bounds__(256, 2) void gemm_tf32_kernel(
    const float* __restrict__ A, const float* __restrict__ W,
    const float* __restrict__ bias, float* __restrict__ C,
    __half* __restrict__ C16, int M, int N, int K)
{
    extern __shared__ float sm[];
    float* sA = sm;                   // [2][128][36]
    float* sW = sm + 2 * GA_STRIDE;   // [2][32][136]

    const int tid  = threadIdx.x;
    const int lane = tid & 31;
    const int warp = tid >> 5;
    const int gid  = lane >> 2;
    const int tig  = lane & 3;
    const int bm   = blockIdx.y * 128;
    const int bn   = blockIdx.x * 128;
    const int wm   = (warp & 3) * 32;
    const int wn   = (warp >> 2) * 64;

    const int a_r = tid >> 3;
    const int a_c = (tid & 7) * 4;
    const int w_r = tid >> 5;
    const int w_c = (tid & 31) * 4;

    const float* Ag = A + (size_t)(bm + a_r) * K + a_c;
    const float* Wg = W + (size_t)w_r * N + bn + w_c;

    float acc[2][8][4] = {};
    const int NC = K / 32;

    {
#pragma unroll
        for (int i = 0; i < 4; i++)
            cpa16(sA + (a_r + i * 32) * 36 + a_c, Ag + (size_t)i * 32 * K);
#pragma unroll
        for (int i = 0; i < 4; i++)
            cpa16(sW + (w_r + i * 8) * 136 + w_c, Wg + (size_t)i * 8 * N);
        cp_commit();
    }

    for (int c = 0; c < NC; ++c) {
        const int buf = c & 1;
        if (c + 1 < NC) {
            float* dA = sA + (buf ^ 1) * GA_STRIDE;
            float* dW = sW + (buf ^ 1) * GW_STRIDE;
            const float* Agc = Ag + (c + 1) * 32;
            const float* Wgc = Wg + (size_t)(c + 1) * 32 * N;
#pragma unroll
            for (int i = 0; i < 4; i++)
                cpa16(dA + (a_r + i * 32) * 36 + a_c, Agc + (size_t)i * 32 * K);
#pragma unroll
            for (int i = 0; i < 4; i++)
                cpa16(dW + (w_r + i * 8) * 136 + w_c, Wgc + (size_t)i * 8 * N);
            cp_commit();
            cp_wait1();
        } else {
            cp_wait0();
        }
        __syncthreads();

        const float* ab = sA + buf * GA_STRIDE;
        const float* wb = sW + buf * GW_STRIDE;
#pragma unroll
        for (int ks = 0; ks < 4; ks++) {
            unsigned af[2][4];
#pragma unroll
            for (int mt = 0; mt < 2; mt++) {
                const float* p = ab + (wm + mt * 16 + gid) * 36 + ks * 8 + tig;
                af[mt][0] = f2tf(p[0]);
                af[mt][1] = f2tf(p[8 * 36]);
                af[mt][2] = f2tf(p[4]);
                af[mt][3] = f2tf(p[8 * 36 + 4]);
            }
            unsigned bf[8][2];
#pragma unroll
            for (int nt = 0; nt < 8; nt++) {
                const float* p = wb + (ks * 8 + tig) * 136 + wn + nt * 8 + gid;
                bf[nt][0] = f2tf(p[0]);
                bf[nt][1] = f2tf(p[4 * 136]);
            }
#pragma unroll
            for (int mt = 0; mt < 2; mt++)
#pragma unroll
                for (int nt = 0; nt < 8; nt++)
                    mma_tf32(acc[mt][nt], af[mt], bf[nt]);
        }
        __syncthreads();
    }

#pragma unroll
    for (int mt = 0; mt < 2; mt++) {
        const int r0 = bm + wm + mt * 16 + gid;
#pragma unroll
        for (int nt = 0; nt < 8; nt++) {
            const int cc = bn + wn + nt * 8 + 2 * tig;
            float2 bb = *(const float2*)(bias + cc);
            float2 v0, v1;
            v0.x = acc[mt][nt][0] + bb.x; v0.y = acc[mt][nt][1] + bb.y;
            v1.x = acc[mt][nt][2] + bb.x; v1.y = acc[mt][nt][3] + bb.y;
            if (C) {
                *(float2*)(C + (size_t)r0 * N + cc) = v0;
                *(float2*)(C + (size_t)(r0 + 8) * N + cc) = v1;
            }
            if (C16) {
                *(__half2*)(C16 + (size_t)r0 * N + cc)       = __floats2half2_rn(v0.x, v0.y);
                *(__half2*)(C16 + (size_t)(r0 + 8) * N + cc) = __floats2half2_rn(v1.x, v1.y);
            }
        }
    }
}

// ---------------------------------------------------------------------------
// Flash attention v3 (causal, fp16 mma m16n8k16 + ldmatrix).
// 128 q-rows/block, 8 warps, warp owns 16 rows (warp-local softmax).
// K/V fp16 in smem, double-buffered cp.async. P staged fp16 per-warp.
// ---------------------------------------------------------------------------
static const int KPH = 72;           // halves per K/V row (144B: conflict-free ldmatrix)
static const int PPH = 72;
static const int AKH = 64 * KPH;     // halves per K (or V) buffer
static const int ATTN_SMEM = (4 * AKH + 8 * 16 * PPH) * 2;  // 55296 B

__global__ __launch_bounds__(256, 2) void attn_f16_kernel(
    const __half* __restrict__ Q, const __half* __restrict__ KV,
    float* __restrict__ ctx)
{
    extern __shared__ float sm[];
    __half* smh = (__half*)sm;
    __half* sK = smh;                 // [2][64][KPH]
    __half* sV = smh + 2 * AKH;       // [2][64][KPH]
    __half* sP = smh + 4 * AKH;       // [8][16][PPH]

    const int qb   = gridDim.x - 1 - blockIdx.x;  // big tiles first
    const int b    = blockIdx.y >> 4;
    const int h    = blockIdx.y & 15;
    const int tid  = threadIdx.x;
    const int lane = tid & 31;
    const int warp = tid >> 5;
    const int gid  = lane >> 2;
    const int tig  = lane & 3;
    const int mb   = warp * 16;
    __half* sPw = sP + warp * 16 * PPH;

    const __half* Qb = Q  + ((size_t)b * SEQ + (size_t)qb * 128 + mb) * DIM + h * HDIM;
    const __half* Kb = KV + (size_t)b * SEQ * KVLD + h * HDIM;

    // prologue: prefetch K/V tile 0 (1024 16B chunks: K:512, V:512)
#pragma unroll
    for (int i = 0; i < 4; i++) {
        int idx = tid + (i << 8);
        int kv = idx >> 9, r = (idx >> 3) & 63, c = idx & 7;
        const __half* src = Kb + (size_t)r * KVLD + c * 8 + (kv ? DIM : 0);
        __half* dst = (kv ? sV : sK) + r * KPH + c * 8;
        cpa16(dst, src);
    }
    cp_commit();

    // stage this warp's Q (16 rows x 64 halves) into its P slice
#pragma unroll
    for (int i = 0; i < 4; i++) {
        int idx = lane + (i << 5);        // 0..127
        int r = idx >> 3, c = idx & 7;
        *(uint4*)(sPw + r * PPH + c * 8) = *(const uint4*)(Qb + (size_t)r * DIM + c * 8);
    }
    __syncwarp();

    // shared-space byte addresses
    const unsigned shP = (unsigned)__cvta_generic_to_shared(sPw);
    const unsigned shK = (unsigned)__cvta_generic_to_shared(sK);
    const unsigned shV = (unsigned)__cvta_generic_to_shared(sV);

    // ldmatrix lane-address components (element offsets, x2 for bytes)
    const int arow = lane & 15;                              // A-frag (Q, P)
    const int acol = (lane >> 4) << 3;
    const int krow = (lane & 7) + ((lane >> 4) << 3);        // K B-frag
    const int kcol = ((lane >> 3) & 1) << 3;
    const int vrow = (lane & 7) + (((lane >> 3) & 1) << 3);  // V B-frag (trans)
    const int vcol = (lane >> 4) << 3;

    const unsigned aoff = (unsigned)((arow * PPH + acol) * 2);
    const unsigned koff = (unsigned)((krow * KPH + kcol) * 2);
    const unsigned voff = (unsigned)((vrow * KPH + vcol) * 2);

    // Q fragments (kept in registers for whole kernel)
    unsigned qf[4][4];
#pragma unroll
    for (int ks = 0; ks < 4; ks++)
        ldm_x4(qf[ks][0], qf[ks][1], qf[ks][2], qf[ks][3], shP + aoff + ks * 32);
    __syncwarp();

    float ms0 = -INFINITY, ms1 = -INFINITY, ls0 = 0.f, ls1 = 0.f;
    float Oacc[8][4] = {};
    const int jmax = 2 * qb + 1;
    const int rg0  = qb * 128 + mb + gid;
    const float sc2 = 0.125f * 1.44269504f;   // scale * log2(e), exp -> ex2

    for (int j = 0; j <= jmax; ++j) {
        const int buf = j & 1;
        cp_wait0();
        __syncthreads();

        if (j < jmax) {
            __half* dK = sK + (buf ^ 1) * AKH;
            __half* dV = sV + (buf ^ 1) * AKH;
            const __half* s0 = Kb + (size_t)(j + 1) * 64 * KVLD;
#pragma unroll
            for (int i = 0; i < 4; i++) {
                int idx = tid + (i << 8);
                int kv = idx >> 9, r = (idx >> 3) & 63, c = idx & 7;
                const __half* src = s0 + (size_t)r * KVLD + c * 8 + (kv ? DIM : 0);
                __half* dst = (kv ? dV : dK) + r * KPH + c * 8;
                cpa16(dst, src);
            }
            cp_commit();
        }

        const unsigned kb = shK + (unsigned)(buf * AKH * 2);
        const unsigned vb = shV + (unsigned)(buf * AKH * 2);

        // S = Q @ K^T : 16x64, K=64 -> 4 ks x 4 np ldmatrix.x4 + 8 mma
        float sacc[8][4] = {};
#pragma unroll
        for (int ks = 0; ks < 4; ks++) {
#pragma unroll
            for (int np = 0; np < 4; np++) {
                unsigned b0, b1, b2, b3;
                ldm_x4(b0, b1, b2, b3, kb + koff + (unsigned)((np * 16 * KPH + ks * 16) * 2));
                unsigned bb0[2] = {b0, b1}, bb1[2] = {b2, b3};
                mma_f16(sacc[np * 2],     qf[ks], bb0);
                mma_f16(sacc[np * 2 + 1], qf[ks], bb1);
            }
        }

        // scale (log2-domain) + causal mask on diagonal tiles
        if (j * 64 + 63 > qb * 128 + mb) {
#pragma unroll
            for (int nt = 0; nt < 8; nt++) {
                const int cg = j * 64 + nt * 8 + 2 * tig;
                sacc[nt][0] = (cg     <= rg0    ) ? sacc[nt][0] * sc2 : -1e30f;
                sacc[nt][1] = (cg + 1 <= rg0    ) ? sacc[nt][1] * sc2 : -1e30f;
                sacc[nt][2] = (cg     <= rg0 + 8) ? sacc[nt][2] * sc2 : -1e30f;
                sacc[nt][3] = (cg + 1 <= rg0 + 8) ? sacc[nt][3] * sc2 : -1e30f;
            }
        } else {
#pragma unroll
            for (int nt = 0; nt < 8; nt++) {
                sacc[nt][0] *= sc2; sacc[nt][1] *= sc2;
                sacc[nt][2] *= sc2; sacc[nt][3] *= sc2;
            }
        }

        // warp-local online softmax (base-2)
        float m0 = -INFINITY, m1 = -INFINITY;
#pragma unroll
        for (int nt = 0; nt < 8; nt++) {
            m0 = fmaxf(m0, fmaxf(sacc[nt][0], sacc[nt][1]));
            m1 = fmaxf(m1, fmaxf(sacc[nt][2], sacc[nt][3]));
        }
        m0 = fmaxf(m0, __shfl_xor_sync(0xffffffffu, m0, 1));
        m0 = fmaxf(m0, __shfl_xor_sync(0xffffffffu, m0, 2));
        m1 = fmaxf(m1, __shfl_xor_sync(0xffffffffu, m1, 1));
        m1 = fmaxf(m1, __shfl_xor_sync(0xffffffffu, m1, 2));
        const float mn0 = fmaxf(ms0, m0);
        const float mn1 = fmaxf(ms1, m1);
        const float a0  = ex2f(ms0 - mn0);
        const float a1  = ex2f(ms1 - mn1);
        ms0 = mn0; ms1 = mn1;
        float rs0 = 0.f, rs1 = 0.f;
#pragma unroll
        for (int nt = 0; nt < 8; nt++) {
            sacc[nt][0] = ex2f(sacc[nt][0] - mn0);
            sacc[nt][1] = ex2f(sacc[nt][1] - mn0);
            sacc[nt][2] = ex2f(sacc[nt][2] - mn1);
            sacc[nt][3] = ex2f(sacc[nt][3] - mn1);
            rs0 += sacc[nt][0] + sacc[nt][1];
            rs1 += sacc[nt][2] + sacc[nt][3];
        }
        rs0 += __shfl_xor_sync(0xffffffffu, rs0, 1);
        rs0 += __shfl_xor_sync(0xffffffffu, rs0, 2);
        rs1 += __shfl_xor_sync(0xffffffffu, rs1, 1);
        rs1 += __shfl_xor_sync(0xffffffffu, rs1, 2);
        ls0 = ls0 * a0 + rs0;
        ls1 = ls1 * a1 + rs1;
#pragma unroll
        for (int nt = 0; nt < 8; nt++) {
            Oacc[nt][0] *= a0; Oacc[nt][1] *= a0;
            Oacc[nt][2] *= a1; Oacc[nt][3] *= a1;
        }

        // P -> warp-private smem as fp16 (accumulator layout)
        __syncwarp();
#pragma unroll
        for (int nt = 0; nt < 8; nt++) {
            *(__half2*)(sPw + gid * PPH + nt * 8 + 2 * tig)       = __floats2half2_rn(sacc[nt][0], sacc[nt][1]);
            *(__half2*)(sPw + (gid + 8) * PPH + nt * 8 + 2 * tig) = __floats2half2_rn(sacc[nt][2], sacc[nt][3]);
        }
        __syncwarp();

        // P fragments
        unsigned pf[4][4];
#pragma unroll
        for (int ks = 0; ks < 4; ks++)
            ldm_x4(pf[ks][0], pf[ks][1], pf[ks][2], pf[ks][3], shP + aoff + ks * 32);
        __syncwarp();

        // O += P @ V : V B-frags via ldmatrix.trans
#pragma unroll
        for (int ks = 0; ks < 4; ks++) {
#pragma unroll
            for (int np = 0; np < 4; np++) {
                unsigned b0, b1, b2, b3;
                ldm_x4t(b0, b1, b2, b3, vb + voff + (unsigned)((ks * 16 * KPH + np * 16) * 2));
                unsigned bb0[2] = {b0, b1}, bb1[2] = {b2, b3};
                mma_f16(Oacc[np * 2],     pf[ks], bb0);
                mma_f16(Oacc[np * 2 + 1], pf[ks], bb1);
            }
        }
    }

    // epilogue: normalize + write ctx (fp32)
    const float inv0 = 1.0f / ls0;
    const float inv1 = 1.0f / ls1;
    float* cb = ctx + ((size_t)b * SEQ + (size_t)qb * 128 + mb) * DIM + h * HDIM;
#pragma unroll
    for (int nt = 0; nt < 8; nt++) {
        const int col = nt * 8 + 2 * tig;
        float2 o0, o1;
        o0.x = Oacc[nt][0] * inv0; o0.y = Oacc[nt][1] * inv0;
        o1.x = Oacc[nt][2] * inv1; o1.y = Oacc[nt][3] * inv1;
        *(float2*)(cb + (size_t)gid * DIM + col)       = o0;
        *(float2*)(cb + (size_t)(gid + 8) * DIM + col) = o1;
    }
}

// ---------------------------------------------------------------------------
extern "C" void kernel_launch(void* const* d_in, const int* in_sizes, int n_in,
                              void* d_out, int out_size)
{
    const float* x      = (const float*)d_in[0];
    // d_in[1] = mask (tril) — causality handled analytically
    const float* w_kvc  = (const float*)d_in[2];
    const float* b_kvc  = (const float*)d_in[3];
    const float* w_kvu  = (const float*)d_in[4];
    const float* b_kvu  = (const float*)d_in[5];
    const float* w_qc   = (const float*)d_in[6];
    const float* b_qc   = (const float*)d_in[7];
    const float* w_qu   = (const float*)d_in[8];
    const float* b_qu   = (const float*)d_in[9];
    const float* w_o    = (const float*)d_in[10];
    const float* b_o    = (const float*)d_in[11];
    float* out = (float*)d_out;

    float *kvlat, *qlat, *ctx;
    __half *kv16, *q16;
    cudaGetSymbolAddress((void**)&kvlat, g_kvlat);
    cudaGetSymbolAddress((void**)&qlat,  g_qlat);
    cudaGetSymbolAddress((void**)&ctx,   g_ctx);
    cudaGetSymbolAddress((void**)&kv16,  g_kv16);
    cudaGetSymbolAddress((void**)&q16,   g_q16);

    cudaFuncSetAttribute(gemm_tf32_kernel, cudaFuncAttributeMaxDynamicSharedMemorySize, GEMM_SMEM);
    cudaFuncSetAttribute(attn_f16_kernel,  cudaFuncAttributeMaxDynamicSharedMemorySize, ATTN_SMEM);

    dim3 t(256);

    // kv_latent = x @ w_kvc + b_kvc                [8192,128] fp32
    gemm_tf32_kernel<<<dim3(LATENT / 128, MTOT / 128), t, GEMM_SMEM>>>(x, w_kvc, b_kvc, kvlat, nullptr, MTOT, LATENT, DIM);
    // kv_up = kv_latent @ w_kvu + b_kvu            [8192,2048] -> fp16 only
    gemm_tf32_kernel<<<dim3(2 * DIM / 128, MTOT / 128), t, GEMM_SMEM>>>(kvlat, w_kvu, b_kvu, nullptr, kv16, MTOT, 2 * DIM, LATENT);
    // q_latent = x @ w_qc + b_qc                   [8192,256] fp32
    gemm_tf32_kernel<<<dim3(QRANK / 128, MTOT / 128), t, GEMM_SMEM>>>(x, w_qc, b_qc, qlat, nullptr, MTOT, QRANK, DIM);
    // Q = q_latent @ w_qu + b_qu                   [8192,1024] -> fp16 only
    gemm_tf32_kernel<<<dim3(DIM / 128, MTOT / 128), t, GEMM_SMEM>>>(qlat, w_qu, b_qu, nullptr, q16, MTOT, DIM, QRANK);

    // attention -> ctx (fp32), fp16 mma inside
    attn_f16_kernel<<<dim3(SEQ / 128, BATCH * NHEAD), t, ATTN_SMEM>>>(q16, kv16, ctx);

    // out = ctx @ w_o + b_o                        [8192,1024] fp32
    gemm_tf32_kernel<<<dim3(DIM / 128, MTOT / 128), t, GEMM_SMEM>>>(ctx, w_o, b_o, out, nullptr, MTOT, DIM, DIM);
}

// round 11
// speedup vs baseline: 1.5440x; 1.5440x over previous
#include <cuda_runtime.h>
#include <cuda_fp16.h>
#include <math.h>

// Problem constants
static const int BATCH  = 4;
static const int SEQ    = 2048;
static const int DIM    = 1024;
static const int NHEAD  = 16;
static const int HDIM   = 64;
static const int LATENT = 128;
static const int QRANK  = 256;
static const int MTOT   = BATCH * SEQ;          // 8192
static const int KVLD   = 2 * DIM;              // 2048

// Scratch (no allocations allowed) ------------------------------------------
__device__ float  g_kvlat[(size_t)MTOT * LATENT];
__device__ float  g_qlat [(size_t)MTOT * QRANK];
__device__ float  g_ctx  [(size_t)MTOT * DIM];
__device__ __half g_kv16 [(size_t)MTOT * 2 * DIM];   // K|V in fp16
__device__ __half g_q16  [(size_t)MTOT * DIM];       // Q in fp16 (pre-scaled)

// ---------------------------------------------------------------------------
// helpers
// ---------------------------------------------------------------------------
__device__ __forceinline__ unsigned f2tf(float x) {
    unsigned u;
    asm("cvt.rna.tf32.f32 %0, %1;" : "=r"(u) : "f"(x));
    return u;
}

__device__ __forceinline__ void mma_tf32(float* d, const unsigned* a, const unsigned* b) {
    asm volatile(
        "mma.sync.aligned.m16n8k8.row.col.f32.tf32.tf32.f32 "
        "{%0,%1,%2,%3}, {%4,%5,%6,%7}, {%8,%9}, {%0,%1,%2,%3};"
        : "+f"(d[0]), "+f"(d[1]), "+f"(d[2]), "+f"(d[3])
        : "r"(a[0]), "r"(a[1]), "r"(a[2]), "r"(a[3]), "r"(b[0]), "r"(b[1]));
}

__device__ __forceinline__ void mma_f16(float* d, const unsigned* a, const unsigned* b) {
    asm volatile(
        "mma.sync.aligned.m16n8k16.row.col.f32.f16.f16.f32 "
        "{%0,%1,%2,%3}, {%4,%5,%6,%7}, {%8,%9}, {%0,%1,%2,%3};"
        : "+f"(d[0]), "+f"(d[1]), "+f"(d[2]), "+f"(d[3])
        : "r"(a[0]), "r"(a[1]), "r"(a[2]), "r"(a[3]), "r"(b[0]), "r"(b[1]));
}

__device__ __forceinline__ void ldm_x4(unsigned& r0, unsigned& r1, unsigned& r2, unsigned& r3,
                                       unsigned addr) {
    asm volatile("ldmatrix.sync.aligned.m8n8.x4.shared.b16 {%0,%1,%2,%3}, [%4];"
        : "=r"(r0), "=r"(r1), "=r"(r2), "=r"(r3) : "r"(addr));
}
__device__ __forceinline__ void ldm_x4t(unsigned& r0, unsigned& r1, unsigned& r2, unsigned& r3,
                                        unsigned addr) {
    asm volatile("ldmatrix.sync.aligned.m8n8.x4.trans.shared.b16 {%0,%1,%2,%3}, [%4];"
        : "=r"(r0), "=r"(r1), "=r"(r2), "=r"(r3) : "r"(addr));
}

__device__ __forceinline__ float ex2f(float x) {
    float y;
    asm("ex2.approx.f32 %0, %1;" : "=f"(y) : "f"(x));
    return y;
}
__device__ __forceinline__ unsigned ex2h2(unsigned x) {
    unsigned y;
    asm("ex2.approx.f16x2 %0, %1;" : "=r"(y) : "r"(x));
    return y;
}
__device__ __forceinline__ unsigned packsub(float a, float b, unsigned mh2) {
    // (half2(a,b) - mh2) as raw bits
    __half2 v = __floats2half2_rn(a, b);
    unsigned vu = *(unsigned*)&v;
    __half2 m = *(__half2*)&mh2;
    __half2 r = __hsub2(*(__half2*)&vu, m);
    return *(unsigned*)&r;
}

__device__ __forceinline__ void cpa16(void* smem, const void* g) {
    unsigned s = (unsigned)__cvta_generic_to_shared(smem);
    asm volatile("cp.async.cg.shared.global [%0], [%1], 16;" :: "r"(s), "l"(g));
}
__device__ __forceinline__ void cp_commit() { asm volatile("cp.async.commit_group;"); }
__device__ __forceinline__ void cp_wait1()  { asm volatile("cp.async.wait_group 1;"); }
__device__ __forceinline__ void cp_wait0()  { asm volatile("cp.async.wait_group 0;"); }

// ---------------------------------------------------------------------------
// tf32 GEMM: C[M,N] = (A[M,K] @ W[K,N] + bias) * oscale. BM=BN=128, BK=32.
// Optional fp32 (C) and/or fp16 (C16) outputs.
// ---------------------------------------------------------------------------
static const int GA_STRIDE = 128 * 36;
static const int GW_STRIDE = 32 * 136;
static const int GEMM_SMEM = (2 * GA_STRIDE + 2 * GW_STRIDE) * 4;  // 71680 B

__global__ __launch_bounds__(256, 2) void gemm_tf32_kernel(
    const float* __restrict__ A, const float* __restrict__ W,
    const float* __restrict__ bias, float* __restrict__ C,
    __half* __restrict__ C16, int M, int N, int K, float oscale)
{
    extern __shared__ float sm[];
    float* sA = sm;                   // [2][128][36]
    float* sW = sm + 2 * GA_STRIDE;   // [2][32][136]

    const int tid  = threadIdx.x;
    const int lane = tid & 31;
    const int warp = tid >> 5;
    const int gid  = lane >> 2;
    const int tig  = lane & 3;
    const int bm   = blockIdx.y * 128;
    const int bn   = blockIdx.x * 128;
    const int wm   = (warp & 3) * 32;
    const int wn   = (warp >> 2) * 64;

    const int a_r = tid >> 3;
    const int a_c = (tid & 7) * 4;
    const int w_r = tid >> 5;
    const int w_c = (tid & 31) * 4;

    const float* Ag = A + (size_t)(bm + a_r) * K + a_c;
    const float* Wg = W + (size_t)w_r * N + bn + w_c;

    float acc[2][8][4] = {};
    const int NC = K / 32;

    {
#pragma unroll
        for (int i = 0; i < 4; i++)
            cpa16(sA + (a_r + i * 32) * 36 + a_c, Ag + (size_t)i * 32 * K);
#pragma unroll
        for (int i = 0; i < 4; i++)
            cpa16(sW + (w_r + i * 8) * 136 + w_c, Wg + (size_t)i * 8 * N);
        cp_commit();
    }

    for (int c = 0; c < NC; ++c) {
        const int buf = c & 1;
        if (c + 1 < NC) {
            float* dA = sA + (buf ^ 1) * GA_STRIDE;
            float* dW = sW + (buf ^ 1) * GW_STRIDE;
            const float* Agc = Ag + (c + 1) * 32;
            const float* Wgc = Wg + (size_t)(c + 1) * 32 * N;
#pragma unroll
            for (int i = 0; i < 4; i++)
                cpa16(dA + (a_r + i * 32) * 36 + a_c, Agc + (size_t)i * 32 * K);
#pragma unroll
            for (int i = 0; i < 4; i++)
                cpa16(dW + (w_r + i * 8) * 136 + w_c, Wgc + (size_t)i * 8 * N);
            cp_commit();
            cp_wait1();
        } else {
            cp_wait0();
        }
        __syncthreads();

        const float* ab = sA + buf * GA_STRIDE;
        const float* wb = sW + buf * GW_STRIDE;
#pragma unroll
        for (int ks = 0; ks < 4; ks++) {
            unsigned af[2][4];
#pragma unroll
            for (int mt = 0; mt < 2; mt++) {
                const float* p = ab + (wm + mt * 16 + gid) * 36 + ks * 8 + tig;
                af[mt][0] = f2tf(p[0]);
                af[mt][1] = f2tf(p[8 * 36]);
                af[mt][2] = f2tf(p[4]);
                af[mt][3] = f2tf(p[8 * 36 + 4]);
            }
            unsigned bf[8][2];
#pragma unroll
            for (int nt = 0; nt < 8; nt++) {
                const float* p = wb + (ks * 8 + tig) * 136 + wn + nt * 8 + gid;
                bf[nt][0] = f2tf(p[0]);
                bf[nt][1] = f2tf(p[4 * 136]);
            }
#pragma unroll
            for (int mt = 0; mt < 2; mt++)
#pragma unroll
                for (int nt = 0; nt < 8; nt++)
                    mma_tf32(acc[mt][nt], af[mt], bf[nt]);
        }
        __syncthreads();
    }

#pragma unroll
    for (int mt = 0; mt < 2; mt++) {
        const int r0 = bm + wm + mt * 16 + gid;
#pragma unroll
        for (int nt = 0; nt < 8; nt++) {
            const int cc = bn + wn + nt * 8 + 2 * tig;
            float2 bb = *(const float2*)(bias + cc);
            float2 v0, v1;
            v0.x = (acc[mt][nt][0] + bb.x) * oscale; v0.y = (acc[mt][nt][1] + bb.y) * oscale;
            v1.x = (acc[mt][nt][2] + bb.x) * oscale; v1.y = (acc[mt][nt][3] + bb.y) * oscale;
            if (C) {
                *(float2*)(C + (size_t)r0 * N + cc) = v0;
                *(float2*)(C + (size_t)(r0 + 8) * N + cc) = v1;
            }
            if (C16) {
                *(__half2*)(C16 + (size_t)r0 * N + cc)       = __floats2half2_rn(v0.x, v0.y);
                *(__half2*)(C16 + (size_t)(r0 + 8) * N + cc) = __floats2half2_rn(v1.x, v1.y);
            }
        }
    }
}

// ---------------------------------------------------------------------------
// Flash attention v4 (causal, fp16 mma, register-resident P, mma row-sums).
// Q pre-scaled by 0.125*log2(e); softmax in base-2 with ex2.f16x2.
// ---------------------------------------------------------------------------
static const int KPH = 72;           // halves per K/V row (144B: conflict-free ldmatrix)
static const int PPH = 72;
static const int AKH = 64 * KPH;     // halves per K (or V) buffer
static const int ATTN_SMEM = (4 * AKH + 8 * 16 * PPH) * 2;  // 55296 B

__global__ __launch_bounds__(256, 2) void attn_f16_kernel(
    const __half* __restrict__ Q, const __half* __restrict__ KV,
    float* __restrict__ ctx)
{
    extern __shared__ float sm[];
    __half* smh = (__half*)sm;
    __half* sK = smh;                 // [2][64][KPH]
    __half* sV = smh + 2 * AKH;       // [2][64][KPH]
    __half* sP = smh + 4 * AKH;       // [8][16][PPH] (Q staging only)

    const int qb   = gridDim.x - 1 - blockIdx.x;  // big tiles first
    const int b    = blockIdx.y >> 4;
    const int h    = blockIdx.y & 15;
    const int tid  = threadIdx.x;
    const int lane = tid & 31;
    const int warp = tid >> 5;
    const int gid  = lane >> 2;
    const int tig  = lane & 3;
    const int mb   = warp * 16;
    __half* sPw = sP + warp * 16 * PPH;

    const __half* Qb = Q  + ((size_t)b * SEQ + (size_t)qb * 128 + mb) * DIM + h * HDIM;
    const __half* Kb = KV + (size_t)b * SEQ * KVLD + h * HDIM;

    // prologue: prefetch K/V tile 0 (1024 16B chunks: K:512, V:512)
#pragma unroll
    for (int i = 0; i < 4; i++) {
        int idx = tid + (i << 8);
        int kv = idx >> 9, r = (idx >> 3) & 63, c = idx & 7;
        const __half* src = Kb + (size_t)r * KVLD + c * 8 + (kv ? DIM : 0);
        __half* dst = (kv ? sV : sK) + r * KPH + c * 8;
        cpa16(dst, src);
    }
    cp_commit();

    // stage this warp's Q (16 rows x 64 halves) into its staging slice
#pragma unroll
    for (int i = 0; i < 4; i++) {
        int idx = lane + (i << 5);        // 0..127
        int r = idx >> 3, c = idx & 7;
        *(uint4*)(sPw + r * PPH + c * 8) = *(const uint4*)(Qb + (size_t)r * DIM + c * 8);
    }
    __syncwarp();

    const unsigned shP = (unsigned)__cvta_generic_to_shared(sPw);
    const unsigned shK = (unsigned)__cvta_generic_to_shared(sK);
    const unsigned shV = (unsigned)__cvta_generic_to_shared(sV);

    // ldmatrix lane-address components
    const int arow = lane & 15;                              // A-frag (Q)
    const int acol = (lane >> 4) << 3;
    const int krow = (lane & 7) + ((lane >> 4) << 3);        // K B-frag
    const int kcol = ((lane >> 3) & 1) << 3;
    const int vrow = (lane & 7) + (((lane >> 3) & 1) << 3);  // V B-frag (trans)
    const int vcol = (lane >> 4) << 3;

    const unsigned aoff = (unsigned)((arow * PPH + acol) * 2);
    const unsigned koff = (unsigned)((krow * KPH + kcol) * 2);
    const unsigned voff = (unsigned)((vrow * KPH + vcol) * 2);

    // Q fragments (registers, whole kernel)
    unsigned qf[4][4];
#pragma unroll
    for (int ks = 0; ks < 4; ks++)
        ldm_x4(qf[ks][0], qf[ks][1], qf[ks][2], qf[ks][3], shP + aoff + ks * 32);
    __syncwarp();

    const unsigned ONES2 = 0x3C003C00u;       // half2(1,1)
    const unsigned onesb[2] = {ONES2, ONES2}; // all-ones B fragment (row sums)

    float ms0 = -INFINITY, ms1 = -INFINITY;
    float Oacc[8][4] = {};
    float lacc[4] = {};                       // [0]=row gid sum, [2]=row gid+8 sum
    const int jmax  = 2 * qb + 1;
    const int rg0   = qb * 128 + mb + gid;
    const int jwtop = qb * 128 + mb + 15;     // warp's last row (skip tiles beyond)

    for (int j = 0; j <= jmax; ++j) {
        const int buf = j & 1;
        cp_wait0();
        __syncthreads();

        if (j < jmax) {
            __half* dK = sK + (buf ^ 1) * AKH;
            __half* dV = sV + (buf ^ 1) * AKH;
            const __half* s0 = Kb + (size_t)(j + 1) * 64 * KVLD;
#pragma unroll
            for (int i = 0; i < 4; i++) {
                int idx = tid + (i << 8);
                int kv = idx >> 9, r = (idx >> 3) & 63, c = idx & 7;
                const __half* src = s0 + (size_t)r * KVLD + c * 8 + (kv ? DIM : 0);
                __half* dst = (kv ? dV : dK) + r * KPH + c * 8;
                cpa16(dst, src);
            }
            cp_commit();
        }

        if (j * 64 > jwtop) continue;   // tile fully masked for this warp

        const unsigned kb = shK + (unsigned)(buf * AKH * 2);
        const unsigned vb = shV + (unsigned)(buf * AKH * 2);

        // S = Q @ K^T  (Q pre-scaled: S already in log2-units)
        float sacc[8][4] = {};
#pragma unroll
        for (int ks = 0; ks < 4; ks++) {
#pragma unroll
            for (int np = 0; np < 4; np++) {
                unsigned b0, b1, b2, b3;
                ldm_x4(b0, b1, b2, b3, kb + koff + (unsigned)((np * 16 * KPH + ks * 16) * 2));
                unsigned bb0[2] = {b0, b1}, bb1[2] = {b2, b3};
                mma_f16(sacc[np * 2],     qf[ks], bb0);
                mma_f16(sacc[np * 2 + 1], qf[ks], bb1);
            }
        }

        // causal mask (diagonal tiles only; no scaling needed)
        if (j * 64 + 63 > qb * 128 + mb) {
#pragma unroll
            for (int nt = 0; nt < 8; nt++) {
                const int cg = j * 64 + nt * 8 + 2 * tig;
                if (cg     > rg0    ) sacc[nt][0] = -1e30f;
                if (cg + 1 > rg0    ) sacc[nt][1] = -1e30f;
                if (cg     > rg0 + 8) sacc[nt][2] = -1e30f;
                if (cg + 1 > rg0 + 8) sacc[nt][3] = -1e30f;
            }
        }

        // warp-local online softmax (base-2), P kept in registers as half2
        float m0 = -INFINITY, m1 = -INFINITY;
#pragma unroll
        for (int nt = 0; nt < 8; nt++) {
            m0 = fmaxf(m0, fmaxf(sacc[nt][0], sacc[nt][1]));
            m1 = fmaxf(m1, fmaxf(sacc[nt][2], sacc[nt][3]));
        }
        m0 = fmaxf(m0, __shfl_xor_sync(0xffffffffu, m0, 1));
        m0 = fmaxf(m0, __shfl_xor_sync(0xffffffffu, m0, 2));
        m1 = fmaxf(m1, __shfl_xor_sync(0xffffffffu, m1, 1));
        m1 = fmaxf(m1, __shfl_xor_sync(0xffffffffu, m1, 2));
        const float mn0 = fmaxf(ms0, m0);
        const float mn1 = fmaxf(ms1, m1);
        const float a0  = ex2f(ms0 - mn0);
        const float a1  = ex2f(ms1 - mn1);
        ms0 = mn0; ms1 = mn1;

        lacc[0] *= a0; lacc[1] *= a0; lacc[2] *= a1; lacc[3] *= a1;
#pragma unroll
        for (int nt = 0; nt < 8; nt++) {
            Oacc[nt][0] *= a0; Oacc[nt][1] *= a0;
            Oacc[nt][2] *= a1; Oacc[nt][3] *= a1;
        }

        __half2 mh0v = __float2half2_rn(mn0);
        __half2 mh1v = __float2half2_rn(mn1);
        unsigned mh0 = *(unsigned*)&mh0v;
        unsigned mh1 = *(unsigned*)&mh1v;

        unsigned ph[8], phb[8];   // P as half2: rows gid / gid+8, cols nt*8+2tig
#pragma unroll
        for (int nt = 0; nt < 8; nt++) {
            ph[nt]  = ex2h2(packsub(sacc[nt][0], sacc[nt][1], mh0));
            phb[nt] = ex2h2(packsub(sacc[nt][2], sacc[nt][3], mh1));
        }

        // O += P @ V  and row-sums l += P @ ones (exact fp32 accumulate)
#pragma unroll
        for (int ks = 0; ks < 4; ks++) {
            unsigned pf[4] = { ph[2 * ks], phb[2 * ks], ph[2 * ks + 1], phb[2 * ks + 1] };
            mma_f16(lacc, pf, onesb);
#pragma unroll
            for (int np = 0; np < 4; np++) {
                unsigned b0, b1, b2, b3;
                ldm_x4t(b0, b1, b2, b3, vb + voff + (unsigned)((ks * 16 * KPH + np * 16) * 2));
                unsigned bb0[2] = {b0, b1}, bb1[2] = {b2, b3};
                mma_f16(Oacc[np * 2],     pf, bb0);
                mma_f16(Oacc[np * 2 + 1], pf, bb1);
            }
        }
    }

    // epilogue: normalize + write ctx (fp32)
    const float inv0 = 1.0f / lacc[0];
    const float inv1 = 1.0f / lacc[2];
    float* cb = ctx + ((size_t)b * SEQ + (size_t)qb * 128 + mb) * DIM + h * HDIM;
#pragma unroll
    for (int nt = 0; nt < 8; nt++) {
        const int col = nt * 8 + 2 * tig;
        float2 o0, o1;
        o0.x = Oacc[nt][0] * inv0; o0.y = Oacc[nt][1] * inv0;
        o1.x = Oacc[nt][2] * inv1; o1.y = Oacc[nt][3] * inv1;
        *(float2*)(cb + (size_t)gid * DIM + col)       = o0;
        *(float2*)(cb + (size_t)(gid + 8) * DIM + col) = o1;
    }
}

// ---------------------------------------------------------------------------
extern "C" void kernel_launch(void* const* d_in, const int* in_sizes, int n_in,
                              void* d_out, int out_size)
{
    const float* x      = (const float*)d_in[0];
    // d_in[1] = mask (tril) — causality handled analytically
    const float* w_kvc  = (const float*)d_in[2];
    const float* b_kvc  = (const float*)d_in[3];
    const float* w_kvu  = (const float*)d_in[4];
    const float* b_kvu  = (const float*)d_in[5];
    const float* w_qc   = (const float*)d_in[6];
    const float* b_qc   = (const float*)d_in[7];
    const float* w_qu   = (const float*)d_in[8];
    const float* b_qu   = (const float*)d_in[9];
    const float* w_o    = (const float*)d_in[10];
    const float* b_o    = (const float*)d_in[11];
    float* out = (float*)d_out;

    float *kvlat, *qlat, *ctx;
    __half *kv16, *q16;
    cudaGetSymbolAddress((void**)&kvlat, g_kvlat);
    cudaGetSymbolAddress((void**)&qlat,  g_qlat);
    cudaGetSymbolAddress((void**)&ctx,   g_ctx);
    cudaGetSymbolAddress((void**)&kv16,  g_kv16);
    cudaGetSymbolAddress((void**)&q16,   g_q16);

    cudaFuncSetAttribute(gemm_tf32_kernel, cudaFuncAttributeMaxDynamicSharedMemorySize, GEMM_SMEM);
    cudaFuncSetAttribute(attn_f16_kernel,  cudaFuncAttributeMaxDynamicSharedMemorySize, ATTN_SMEM);

    dim3 t(256);
    const int MH = MTOT / 2;
    const float QSCALE = 0.125f * 1.44269504088896f;  // 1/sqrt(64) * log2(e)

    // kv_latent = x @ w_kvc + b_kvc  [8192,128] fp32 — split so attn = launch 5
    gemm_tf32_kernel<<<dim3(LATENT / 128, MH / 128), t, GEMM_SMEM>>>(
        x, w_kvc, b_kvc, kvlat, nullptr, MH, LATENT, DIM, 1.0f);
    gemm_tf32_kernel<<<dim3(LATENT / 128, MH / 128), t, GEMM_SMEM>>>(
        x + (size_t)MH * DIM, w_kvc, b_kvc, kvlat + (size_t)MH * LATENT, nullptr, MH, LATENT, DIM, 1.0f);
    // kv_up = kv_latent @ w_kvu + b_kvu   [8192,2048] -> fp16
    gemm_tf32_kernel<<<dim3(2 * DIM / 128, MTOT / 128), t, GEMM_SMEM>>>(
        kvlat, w_kvu, b_kvu, nullptr, kv16, MTOT, 2 * DIM, LATENT, 1.0f);
    // q_latent = x @ w_qc + b_qc          [8192,256] fp32
    gemm_tf32_kernel<<<dim3(QRANK / 128, MTOT / 128), t, GEMM_SMEM>>>(
        x, w_qc, b_qc, qlat, nullptr, MTOT, QRANK, DIM, 1.0f);
    // Q = (q_latent @ w_qu + b_qu) * QSCALE  [8192,1024] -> fp16
    gemm_tf32_kernel<<<dim3(DIM / 128, MTOT / 128), t, GEMM_SMEM>>>(
        qlat, w_qu, b_qu, nullptr, q16, MTOT, DIM, QRANK, QSCALE);

    // attention -> ctx (launch index 5: captured by ncu -s 5 -c 1)
    attn_f16_kernel<<<dim3(SEQ / 128, BATCH * NHEAD), t, ATTN_SMEM>>>(q16, kv16, ctx);

    // out = ctx @ w_o + b_o               [8192,1024] fp32
    gemm_tf32_kernel<<<dim3(DIM / 128, MTOT / 128), t, GEMM_SMEM>>>(
        ctx, w_o, b_o, out, nullptr, MTOT, DIM, DIM, 1.0f);
}

// round 13
// speedup vs baseline: 2.3880x; 1.5467x over previous
#include <cuda_runtime.h>
#include <cuda_fp16.h>
#include <math.h>

// Problem constants
static const int BATCH  = 4;
static const int SEQ    = 2048;
static const int DIM    = 1024;
static const int NHEAD  = 16;
static const int HDIM   = 64;
static const int LATENT = 128;
static const int QRANK  = 256;
static const int MTOT   = BATCH * SEQ;          // 8192
static const int KVLD   = 2 * DIM;              // 2048

// Scratch (no allocations allowed) ------------------------------------------
__device__ __half g_x16    [(size_t)MTOT * DIM];
__device__ __half g_kvlat16[(size_t)MTOT * LATENT];
__device__ __half g_qlat16 [(size_t)MTOT * QRANK];
__device__ __half g_kv16   [(size_t)MTOT * 2 * DIM];
__device__ __half g_q16    [(size_t)MTOT * DIM];
__device__ __half g_ctx16  [(size_t)MTOT * DIM];
__device__ __half g_wkvc16 [DIM * LATENT];
__device__ __half g_wkvu16 [LATENT * 2 * DIM];
__device__ __half g_wqc16  [DIM * QRANK];
__device__ __half g_wqu16  [QRANK * DIM];
__device__ __half g_wo16   [DIM * DIM];

// ---------------------------------------------------------------------------
// helpers
// ---------------------------------------------------------------------------
__device__ __forceinline__ void mma_f16(float* d, const unsigned* a, const unsigned* b) {
    asm volatile(
        "mma.sync.aligned.m16n8k16.row.col.f32.f16.f16.f32 "
        "{%0,%1,%2,%3}, {%4,%5,%6,%7}, {%8,%9}, {%0,%1,%2,%3};"
        : "+f"(d[0]), "+f"(d[1]), "+f"(d[2]), "+f"(d[3])
        : "r"(a[0]), "r"(a[1]), "r"(a[2]), "r"(a[3]), "r"(b[0]), "r"(b[1]));
}

__device__ __forceinline__ void ldm_x4(unsigned& r0, unsigned& r1, unsigned& r2, unsigned& r3,
                                       unsigned addr) {
    asm volatile("ldmatrix.sync.aligned.m8n8.x4.shared.b16 {%0,%1,%2,%3}, [%4];"
        : "=r"(r0), "=r"(r1), "=r"(r2), "=r"(r3) : "r"(addr));
}
__device__ __forceinline__ void ldm_x4t(unsigned& r0, unsigned& r1, unsigned& r2, unsigned& r3,
                                        unsigned addr) {
    asm volatile("ldmatrix.sync.aligned.m8n8.x4.trans.shared.b16 {%0,%1,%2,%3}, [%4];"
        : "=r"(r0), "=r"(r1), "=r"(r2), "=r"(r3) : "r"(addr));
}

__device__ __forceinline__ float ex2f(float x) {
    float y;
    asm("ex2.approx.f32 %0, %1;" : "=f"(y) : "f"(x));
    return y;
}
__device__ __forceinline__ unsigned ex2h2(unsigned x) {
    unsigned y;
    asm("ex2.approx.f16x2 %0, %1;" : "=r"(y) : "r"(x));
    return y;
}
__device__ __forceinline__ unsigned packsub(float a, float b, unsigned mh2) {
    __half2 v = __floats2half2_rn(a, b);
    unsigned vu = *(unsigned*)&v;
    __half2 m = *(__half2*)&mh2;
    __half2 r = __hsub2(*(__half2*)&vu, m);
    return *(unsigned*)&r;
}

__device__ __forceinline__ void cpa16(void* smem, const void* g) {
    unsigned s = (unsigned)__cvta_generic_to_shared(smem);
    asm volatile("cp.async.cg.shared.global [%0], [%1], 16;" :: "r"(s), "l"(g));
}
__device__ __forceinline__ void cp_commit() { asm volatile("cp.async.commit_group;"); }
__device__ __forceinline__ void cp_wait1()  { asm volatile("cp.async.wait_group 1;"); }
__device__ __forceinline__ void cp_wait0()  { asm volatile("cp.async.wait_group 0;"); }

// ---------------------------------------------------------------------------
// cvt: fp32 -> fp16 for x and the 5 weight matrices (one launch)
// ---------------------------------------------------------------------------
__global__ void cvt6_kernel(
    const float* s0, __half* d0, int n0, const float* s1, __half* d1, int n1,
    const float* s2, __half* d2, int n2, const float* s3, __half* d3, int n3,
    const float* s4, __half* d4, int n4, const float* s5, __half* d5, int n5)
{
    const int t = blockIdx.x * blockDim.x + threadIdx.x;
    const int stride = gridDim.x * blockDim.x;
#define CV6(s, d, n) \
    for (int i = t; i < (n) / 2; i += stride) { \
        float2 v = ((const float2*)(s))[i]; \
        ((__half2*)(d))[i] = __floats2half2_rn(v.x, v.y); \
    }
    CV6(s0, d0, n0); CV6(s1, d1, n1); CV6(s2, d2, n2);
    CV6(s3, d3, n3); CV6(s4, d4, n4); CV6(s5, d5, n5);
#undef CV6
}

// ---------------------------------------------------------------------------
// fp16 GEMM: out = (A[M,K] @ W[K,N] + bias) * oscale. BM=BN=128, BK=64,
// 256 threads, ldmatrix + mma.m16n8k16. Optional fused second weight set
// (W2/bias2/C16_2 with width N2) sharing the same A tile (extra col-blocks).
// Requires K%64==0, N,N2 %128==0.
// ---------------------------------------------------------------------------
static const int HA_STRIDE = 128 * 72;   // halves per A buffer (144B rows)
static const int HW_STRIDE = 64 * 136;   // halves per W buffer (272B rows)
static const int GEMM16_SMEM = (2 * HA_STRIDE + 2 * HW_STRIDE) * 2;  // 71680 B

__global__ __launch_bounds__(256, 2) void gemm_f16_kernel(
    const __half* __restrict__ A, const __half* __restrict__ W,
    const float* __restrict__ bias, float* __restrict__ C,
    __half* __restrict__ C16, int M, int N, int K, float oscale,
    const __half* __restrict__ W2, const float* __restrict__ bias2,
    __half* __restrict__ C16_2, int N2)
{
    extern __shared__ __half smh[];
    __half* sA = smh;                   // [2][128][72]
    __half* sW = smh + 2 * HA_STRIDE;   // [2][64][136]

    const int tid  = threadIdx.x;
    const int lane = tid & 31;
    const int warp = tid >> 5;
    const int gid  = lane >> 2;
    const int tig  = lane & 3;
    const int bm   = blockIdx.y * 128;
    const int wm   = (warp & 3) * 32;
    const int wn   = (warp >> 2) * 64;

    // select weight set (fused second matrix on high col-blocks)
    const __half* Wp; const float* bp; float* Cp; __half* C16p; int Np, bnl;
    if (W2 == nullptr || blockIdx.x < (unsigned)(N / 128)) {
        Wp = W;  bp = bias;  Cp = C;       C16p = C16;   Np = N;  bnl = blockIdx.x * 128;
    } else {
        Wp = W2; bp = bias2; Cp = nullptr; C16p = C16_2; Np = N2; bnl = (blockIdx.x - N / 128) * 128;
    }

    // loaders: A 1024 chunks (128 rows x 8), W 1024 chunks (64 rows x 16)
    const int a_r = tid >> 1;              // base rows via idx below
    (void)a_r;

    float acc[2][8][4] = {};
    const int NC = K / 64;

    // prologue
#pragma unroll
    for (int i = 0; i < 4; i++) {
        int idx = tid + (i << 8);
        int r = idx >> 3, c = idx & 7;
        cpa16(sA + r * 72 + c * 8, A + (size_t)(bm + r) * K + c * 8);
    }
#pragma unroll
    for (int i = 0; i < 4; i++) {
        int idx = tid + (i << 8);
        int r = idx >> 4, c = idx & 15;
        cpa16(sW + r * 136 + c * 8, Wp + (size_t)r * Np + bnl + c * 8);
    }
    cp_commit();

    const unsigned shA = (unsigned)__cvta_generic_to_shared(sA);
    const unsigned shW = (unsigned)__cvta_generic_to_shared(sW);

    // ldmatrix lane addressing
    const int arow = lane & 15;
    const int acol = (lane >> 4) << 3;
    const int brow = (lane & 7) + (((lane >> 3) & 1) << 3);
    const int bcol = (lane >> 4) << 3;

    for (int c = 0; c < NC; ++c) {
        const int buf = c & 1;
        if (c + 1 < NC) {
            __half* dA = sA + (buf ^ 1) * HA_STRIDE;
            __half* dW = sW + (buf ^ 1) * HW_STRIDE;
            const __half* Ac = A + (size_t)(c + 1) * 64;
            const __half* Wc = Wp + (size_t)(c + 1) * 64 * Np;
#pragma unroll
            for (int i = 0; i < 4; i++) {
                int idx = tid + (i << 8);
                int r = idx >> 3, cc = idx & 7;
                cpa16(dA + r * 72 + cc * 8, Ac + (size_t)(bm + r) * K + cc * 8);
            }
#pragma unroll
            for (int i = 0; i < 4; i++) {
                int idx = tid + (i << 8);
                int r = idx >> 4, cc = idx & 15;
                cpa16(dW + r * 136 + cc * 8, Wc + (size_t)r * Np + bnl + cc * 8);
            }
            cp_commit();
            cp_wait1();
        } else {
            cp_wait0();
        }
        __syncthreads();

        const unsigned ab = shA + (unsigned)(buf * HA_STRIDE * 2);
        const unsigned wb = shW + (unsigned)(buf * HW_STRIDE * 2);

#pragma unroll
        for (int ks = 0; ks < 4; ks++) {
            unsigned af[2][4];
#pragma unroll
            for (int mt = 0; mt < 2; mt++)
                ldm_x4(af[mt][0], af[mt][1], af[mt][2], af[mt][3],
                       ab + (unsigned)(((wm + mt * 16 + arow) * 72 + ks * 16 + acol) * 2));
#pragma unroll
            for (int np = 0; np < 4; np++) {
                unsigned b0, b1, b2, b3;
                ldm_x4t(b0, b1, b2, b3,
                        wb + (unsigned)(((ks * 16 + brow) * 136 + wn + np * 16 + bcol) * 2));
                unsigned bb0[2] = {b0, b1}, bb1[2] = {b2, b3};
#pragma unroll
                for (int mt = 0; mt < 2; mt++) {
                    mma_f16(acc[mt][np * 2],     af[mt], bb0);
                    mma_f16(acc[mt][np * 2 + 1], af[mt], bb1);
                }
            }
        }
        __syncthreads();
    }

    // epilogue
#pragma unroll
    for (int mt = 0; mt < 2; mt++) {
        const int r0 = bm + wm + mt * 16 + gid;
#pragma unroll
        for (int nt = 0; nt < 8; nt++) {
            const int cc = bnl + wn + nt * 8 + 2 * tig;
            float2 bb = *(const float2*)(bp + cc);
            float2 v0, v1;
            v0.x = (acc[mt][nt][0] + bb.x) * oscale; v0.y = (acc[mt][nt][1] + bb.y) * oscale;
            v1.x = (acc[mt][nt][2] + bb.x) * oscale; v1.y = (acc[mt][nt][3] + bb.y) * oscale;
            if (Cp) {
                *(float2*)(Cp + (size_t)r0 * Np + cc) = v0;
                *(float2*)(Cp + (size_t)(r0 + 8) * Np + cc) = v1;
            }
            if (C16p) {
                *(__half2*)(C16p + (size_t)r0 * Np + cc)       = __floats2half2_rn(v0.x, v0.y);
                *(__half2*)(C16p + (size_t)(r0 + 8) * Np + cc) = __floats2half2_rn(v1.x, v1.y);
            }
        }
    }
}

// ---------------------------------------------------------------------------
// Flash attention v4 (causal, fp16 mma, register-resident P, mma row-sums).
// Q pre-scaled by 0.125*log2(e); softmax in base-2 with ex2.f16x2.
// Output ctx written fp16.
// ---------------------------------------------------------------------------
static const int KPH = 72;
static const int PPH = 72;
static const int AKH = 64 * KPH;
static const int ATTN_SMEM = (4 * AKH + 8 * 16 * PPH) * 2;  // 55296 B

__global__ __launch_bounds__(256, 2) void attn_f16_kernel(
    const __half* __restrict__ Q, const __half* __restrict__ KV,
    __half* __restrict__ ctx)
{
    extern __shared__ __half smh2[];
    __half* sK = smh2;
    __half* sV = smh2 + 2 * AKH;
    __half* sP = smh2 + 4 * AKH;

    const int qb   = gridDim.x - 1 - blockIdx.x;
    const int b    = blockIdx.y >> 4;
    const int h    = blockIdx.y & 15;
    const int tid  = threadIdx.x;
    const int lane = tid & 31;
    const int warp = tid >> 5;
    const int gid  = lane >> 2;
    const int tig  = lane & 3;
    const int mb   = warp * 16;
    __half* sPw = sP + warp * 16 * PPH;

    const __half* Qb = Q  + ((size_t)b * SEQ + (size_t)qb * 128 + mb) * DIM + h * HDIM;
    const __half* Kb = KV + (size_t)b * SEQ * KVLD + h * HDIM;

#pragma unroll
    for (int i = 0; i < 4; i++) {
        int idx = tid + (i << 8);
        int kv = idx >> 9, r = (idx >> 3) & 63, c = idx & 7;
        const __half* src = Kb + (size_t)r * KVLD + c * 8 + (kv ? DIM : 0);
        __half* dst = (kv ? sV : sK) + r * KPH + c * 8;
        cpa16(dst, src);
    }
    cp_commit();

#pragma unroll
    for (int i = 0; i < 4; i++) {
        int idx = lane + (i << 5);
        int r = idx >> 3, c = idx & 7;
        *(uint4*)(sPw + r * PPH + c * 8) = *(const uint4*)(Qb + (size_t)r * DIM + c * 8);
    }
    __syncwarp();

    const unsigned shP = (unsigned)__cvta_generic_to_shared(sPw);
    const unsigned shK = (unsigned)__cvta_generic_to_shared(sK);
    const unsigned shV = (unsigned)__cvta_generic_to_shared(sV);

    const int arow = lane & 15;
    const int acol = (lane >> 4) << 3;
    const int krow = (lane & 7) + ((lane >> 4) << 3);
    const int kcol = ((lane >> 3) & 1) << 3;
    const int vrow = (lane & 7) + (((lane >> 3) & 1) << 3);
    const int vcol = (lane >> 4) << 3;

    const unsigned aoff = (unsigned)((arow * PPH + acol) * 2);
    const unsigned koff = (unsigned)((krow * KPH + kcol) * 2);
    const unsigned voff = (unsigned)((vrow * KPH + vcol) * 2);

    unsigned qf[4][4];
#pragma unroll
    for (int ks = 0; ks < 4; ks++)
        ldm_x4(qf[ks][0], qf[ks][1], qf[ks][2], qf[ks][3], shP + aoff + ks * 32);
    __syncwarp();

    const unsigned ONES2 = 0x3C003C00u;
    const unsigned onesb[2] = {ONES2, ONES2};

    float ms0 = -INFINITY, ms1 = -INFINITY;
    float Oacc[8][4] = {};
    float lacc[4] = {};
    const int jmax  = 2 * qb + 1;
    const int rg0   = qb * 128 + mb + gid;
    const int jwtop = qb * 128 + mb + 15;

    for (int j = 0; j <= jmax; ++j) {
        const int buf = j & 1;
        cp_wait0();
        __syncthreads();

        if (j < jmax) {
            __half* dK = sK + (buf ^ 1) * AKH;
            __half* dV = sV + (buf ^ 1) * AKH;
            const __half* s0 = Kb + (size_t)(j + 1) * 64 * KVLD;
#pragma unroll
            for (int i = 0; i < 4; i++) {
                int idx = tid + (i << 8);
                int kv = idx >> 9, r = (idx >> 3) & 63, c = idx & 7;
                const __half* src = s0 + (size_t)r * KVLD + c * 8 + (kv ? DIM : 0);
                __half* dst = (kv ? dV : dK) + r * KPH + c * 8;
                cpa16(dst, src);
            }
            cp_commit();
        }

        if (j * 64 > jwtop) continue;

        const unsigned kb = shK + (unsigned)(buf * AKH * 2);
        const unsigned vb = shV + (unsigned)(buf * AKH * 2);

        float sacc[8][4] = {};
#pragma unroll
        for (int ks = 0; ks < 4; ks++) {
#pragma unroll
            for (int np = 0; np < 4; np++) {
                unsigned b0, b1, b2, b3;
                ldm_x4(b0, b1, b2, b3, kb + koff + (unsigned)((np * 16 * KPH + ks * 16) * 2));
                unsigned bb0[2] = {b0, b1}, bb1[2] = {b2, b3};
                mma_f16(sacc[np * 2],     qf[ks], bb0);
                mma_f16(sacc[np * 2 + 1], qf[ks], bb1);
            }
        }

        if (j * 64 + 63 > qb * 128 + mb) {
#pragma unroll
            for (int nt = 0; nt < 8; nt++) {
                const int cg = j * 64 + nt * 8 + 2 * tig;
                if (cg     > rg0    ) sacc[nt][0] = -1e30f;
                if (cg + 1 > rg0    ) sacc[nt][1] = -1e30f;
                if (cg     > rg0 + 8) sacc[nt][2] = -1e30f;
                if (cg + 1 > rg0 + 8) sacc[nt][3] = -1e30f;
            }
        }

        float m0 = -INFINITY, m1 = -INFINITY;
#pragma unroll
        for (int nt = 0; nt < 8; nt++) {
            m0 = fmaxf(m0, fmaxf(sacc[nt][0], sacc[nt][1]));
            m1 = fmaxf(m1, fmaxf(sacc[nt][2], sacc[nt][3]));
        }
        m0 = fmaxf(m0, __shfl_xor_sync(0xffffffffu, m0, 1));
        m0 = fmaxf(m0, __shfl_xor_sync(0xffffffffu, m0, 2));
        m1 = fmaxf(m1, __shfl_xor_sync(0xffffffffu, m1, 1));
        m1 = fmaxf(m1, __shfl_xor_sync(0xffffffffu, m1, 2));
        const float mn0 = fmaxf(ms0, m0);
        const float mn1 = fmaxf(ms1, m1);
        const float a0  = ex2f(ms0 - mn0);
        const float a1  = ex2f(ms1 - mn1);
        ms0 = mn0; ms1 = mn1;

        lacc[0] *= a0; lacc[1] *= a0; lacc[2] *= a1; lacc[3] *= a1;
#pragma unroll
        for (int nt = 0; nt < 8; nt++) {
            Oacc[nt][0] *= a0; Oacc[nt][1] *= a0;
            Oacc[nt][2] *= a1; Oacc[nt][3] *= a1;
        }

        __half2 mh0v = __float2half2_rn(mn0);
        __half2 mh1v = __float2half2_rn(mn1);
        unsigned mh0 = *(unsigned*)&mh0v;
        unsigned mh1 = *(unsigned*)&mh1v;

        unsigned ph[8], phb[8];
#pragma unroll
        for (int nt = 0; nt < 8; nt++) {
            ph[nt]  = ex2h2(packsub(sacc[nt][0], sacc[nt][1], mh0));
            phb[nt] = ex2h2(packsub(sacc[nt][2], sacc[nt][3], mh1));
        }

#pragma unroll
        for (int ks = 0; ks < 4; ks++) {
            unsigned pf[4] = { ph[2 * ks], phb[2 * ks], ph[2 * ks + 1], phb[2 * ks + 1] };
            mma_f16(lacc, pf, onesb);
#pragma unroll
            for (int np = 0; np < 4; np++) {
                unsigned b0, b1, b2, b3;
                ldm_x4t(b0, b1, b2, b3, vb + voff + (unsigned)((ks * 16 * KPH + np * 16) * 2));
                unsigned bb0[2] = {b0, b1}, bb1[2] = {b2, b3};
                mma_f16(Oacc[np * 2],     pf, bb0);
                mma_f16(Oacc[np * 2 + 1], pf, bb1);
            }
        }
    }

    // epilogue: normalize + write ctx (fp16)
    const float inv0 = 1.0f / lacc[0];
    const float inv1 = 1.0f / lacc[2];
    __half* cb = ctx + ((size_t)b * SEQ + (size_t)qb * 128 + mb) * DIM + h * HDIM;
#pragma unroll
    for (int nt = 0; nt < 8; nt++) {
        const int col = nt * 8 + 2 * tig;
        *(__half2*)(cb + (size_t)gid * DIM + col)       = __floats2half2_rn(Oacc[nt][0] * inv0, Oacc[nt][1] * inv0);
        *(__half2*)(cb + (size_t)(gid + 8) * DIM + col) = __floats2half2_rn(Oacc[nt][2] * inv1, Oacc[nt][3] * inv1);
    }
}

// ---------------------------------------------------------------------------
extern "C" void kernel_launch(void* const* d_in, const int* in_sizes, int n_in,
                              void* d_out, int out_size)
{
    const float* x      = (const float*)d_in[0];
    // d_in[1] = mask (tril) — causality handled analytically
    const float* w_kvc  = (const float*)d_in[2];
    const float* b_kvc  = (const float*)d_in[3];
    const float* w_kvu  = (const float*)d_in[4];
    const float* b_kvu  = (const float*)d_in[5];
    const float* w_qc   = (const float*)d_in[6];
    const float* b_qc   = (const float*)d_in[7];
    const float* w_qu   = (const float*)d_in[8];
    const float* b_qu   = (const float*)d_in[9];
    const float* w_o    = (const float*)d_in[10];
    const float* b_o    = (const float*)d_in[11];
    float* out = (float*)d_out;

    __half *x16, *kvlat16, *qlat16, *kv16, *q16, *ctx16;
    __half *wkvc16, *wkvu16, *wqc16, *wqu16, *wo16;
    cudaGetSymbolAddress((void**)&x16,     g_x16);
    cudaGetSymbolAddress((void**)&kvlat16, g_kvlat16);
    cudaGetSymbolAddress((void**)&qlat16,  g_qlat16);
    cudaGetSymbolAddress((void**)&kv16,    g_kv16);
    cudaGetSymbolAddress((void**)&q16,     g_q16);
    cudaGetSymbolAddress((void**)&ctx16,   g_ctx16);
    cudaGetSymbolAddress((void**)&wkvc16,  g_wkvc16);
    cudaGetSymbolAddress((void**)&wkvu16,  g_wkvu16);
    cudaGetSymbolAddress((void**)&wqc16,   g_wqc16);
    cudaGetSymbolAddress((void**)&wqu16,   g_wqu16);
    cudaGetSymbolAddress((void**)&wo16,    g_wo16);

    cudaFuncSetAttribute(gemm_f16_kernel, cudaFuncAttributeMaxDynamicSharedMemorySize, GEMM16_SMEM);
    cudaFuncSetAttribute(attn_f16_kernel, cudaFuncAttributeMaxDynamicSharedMemorySize, ATTN_SMEM);

    dim3 t(256);
    const float QSCALE = 0.125f * 1.44269504088896f;  // 1/sqrt(64) * log2(e)

    // (0) convert x + all 5 weight matrices to fp16
    cvt6_kernel<<<1024, 256>>>(
        x,     x16,    MTOT * DIM,
        w_kvc, wkvc16, DIM * LATENT,
        w_kvu, wkvu16, LATENT * 2 * DIM,
        w_qc,  wqc16,  DIM * QRANK,
        w_qu,  wqu16,  QRANK * DIM,
        w_o,   wo16,   DIM * DIM);

    // (1) fused: kv_latent = x@w_kvc+b_kvc [8192,128] AND q_latent = x@w_qc+b_qc [8192,256]
    gemm_f16_kernel<<<dim3((LATENT + QRANK) / 128, MTOT / 128), t, GEMM16_SMEM>>>(
        x16, wkvc16, b_kvc, nullptr, kvlat16, MTOT, LATENT, DIM, 1.0f,
        wqc16, b_qc, qlat16, QRANK);

    // (2) kv_up = kv_latent @ w_kvu + b_kvu   [8192,2048] fp16
    gemm_f16_kernel<<<dim3(2 * DIM / 128, MTOT / 128), t, GEMM16_SMEM>>>(
        kvlat16, wkvu16, b_kvu, nullptr, kv16, MTOT, 2 * DIM, LATENT, 1.0f,
        nullptr, nullptr, nullptr, 0);

    // (3) Q = (q_latent @ w_qu + b_qu) * QSCALE  [8192,1024] fp16  (profiled slot)
    gemm_f16_kernel<<<dim3(DIM / 128, MTOT / 128), t, GEMM16_SMEM>>>(
        qlat16, wqu16, b_qu, nullptr, q16, MTOT, DIM, QRANK, QSCALE,
        nullptr, nullptr, nullptr, 0);

    // (4) attention -> ctx16
    attn_f16_kernel<<<dim3(SEQ / 128, BATCH * NHEAD), t, ATTN_SMEM>>>(q16, kv16, ctx16);

    // (5) out = ctx @ w_o + b_o  [8192,1024] fp32
    gemm_f16_kernel<<<dim3(DIM / 128, MTOT / 128), t, GEMM16_SMEM>>>(
        ctx16, wo16, b_o, out, nullptr, MTOT, DIM, DIM, 1.0f,
        nullptr, nullptr, nullptr, 0);
}

// round 15
// speedup vs baseline: 2.3883x; 1.0001x over previous
#include <cuda_runtime.h>
#include <cuda_fp16.h>
#include <math.h>

// Problem constants
static const int BATCH  = 4;
static const int SEQ    = 2048;
static const int DIM    = 1024;
static const int NHEAD  = 16;
static const int HDIM   = 64;
static const int LATENT = 128;
static const int QRANK  = 256;
static const int MTOT   = BATCH * SEQ;          // 8192
static const int KVLD   = 2 * DIM;              // 2048

// Scratch (no allocations allowed) ------------------------------------------
__device__ __half g_x16    [(size_t)MTOT * DIM];
__device__ __half g_kvlat16[(size_t)MTOT * LATENT];
__device__ __half g_qlat16 [(size_t)MTOT * QRANK];
__device__ __half g_kv16   [(size_t)MTOT * 2 * DIM];
__device__ __half g_q16    [(size_t)MTOT * DIM];
__device__ __half g_ctx16  [(size_t)MTOT * DIM];
__device__ __half g_wkvc16 [DIM * LATENT];
__device__ __half g_wkvu16 [LATENT * 2 * DIM];
__device__ __half g_wqc16  [DIM * QRANK];
__device__ __half g_wqu16  [QRANK * DIM];
__device__ __half g_wo16   [DIM * DIM];

// ---------------------------------------------------------------------------
// helpers
// ---------------------------------------------------------------------------
__device__ __forceinline__ void mma_f16(float* d, const unsigned* a, const unsigned* b) {
    asm volatile(
        "mma.sync.aligned.m16n8k16.row.col.f32.f16.f16.f32 "
        "{%0,%1,%2,%3}, {%4,%5,%6,%7}, {%8,%9}, {%0,%1,%2,%3};"
        : "+f"(d[0]), "+f"(d[1]), "+f"(d[2]), "+f"(d[3])
        : "r"(a[0]), "r"(a[1]), "r"(a[2]), "r"(a[3]), "r"(b[0]), "r"(b[1]));
}

__device__ __forceinline__ void ldm_x4(unsigned& r0, unsigned& r1, unsigned& r2, unsigned& r3,
                                       unsigned addr) {
    asm volatile("ldmatrix.sync.aligned.m8n8.x4.shared.b16 {%0,%1,%2,%3}, [%4];"
        : "=r"(r0), "=r"(r1), "=r"(r2), "=r"(r3) : "r"(addr));
}
__device__ __forceinline__ void ldm_x4t(unsigned& r0, unsigned& r1, unsigned& r2, unsigned& r3,
                                        unsigned addr) {
    asm volatile("ldmatrix.sync.aligned.m8n8.x4.trans.shared.b16 {%0,%1,%2,%3}, [%4];"
        : "=r"(r0), "=r"(r1), "=r"(r2), "=r"(r3) : "r"(addr));
}

__device__ __forceinline__ float ex2f(float x) {
    float y;
    asm("ex2.approx.f32 %0, %1;" : "=f"(y) : "f"(x));
    return y;
}
__device__ __forceinline__ unsigned ex2h2(unsigned x) {
    unsigned y;
    asm("ex2.approx.f16x2 %0, %1;" : "=r"(y) : "r"(x));
    return y;
}
__device__ __forceinline__ unsigned packsub(float a, float b, unsigned mh2) {
    __half2 v = __floats2half2_rn(a, b);
    unsigned vu = *(unsigned*)&v;
    __half2 m = *(__half2*)&mh2;
    __half2 r = __hsub2(*(__half2*)&vu, m);
    return *(unsigned*)&r;
}

__device__ __forceinline__ void cpa16(void* smem, const void* g) {
    unsigned s = (unsigned)__cvta_generic_to_shared(smem);
    asm volatile("cp.async.cg.shared.global [%0], [%1], 16;" :: "r"(s), "l"(g));
}
__device__ __forceinline__ void cp_commit() { asm volatile("cp.async.commit_group;"); }
__device__ __forceinline__ void cp_wait1()  { asm volatile("cp.async.wait_group 1;"); }
__device__ __forceinline__ void cp_wait0()  { asm volatile("cp.async.wait_group 0;"); }

// ---------------------------------------------------------------------------
// cvt: fp32 -> fp16 for x and the 5 weight matrices (one launch)
// ---------------------------------------------------------------------------
__global__ void cvt6_kernel(
    const float* s0, __half* d0, int n0, const float* s1, __half* d1, int n1,
    const float* s2, __half* d2, int n2, const float* s3, __half* d3, int n3,
    const float* s4, __half* d4, int n4, const float* s5, __half* d5, int n5)
{
    const int t = blockIdx.x * blockDim.x + threadIdx.x;
    const int stride = gridDim.x * blockDim.x;
#define CV6(s, d, n) \
    for (int i = t; i < (n) / 2; i += stride) { \
        float2 v = ((const float2*)(s))[i]; \
        ((__half2*)(d))[i] = __floats2half2_rn(v.x, v.y); \
    }
    CV6(s0, d0, n0); CV6(s1, d1, n1); CV6(s2, d2, n2);
    CV6(s3, d3, n3); CV6(s4, d4, n4); CV6(s5, d5, n5);
#undef CV6
}

// ---------------------------------------------------------------------------
// fp16 GEMM, dual-problem: column-blocks [0, N/128) compute problem 1
// (A,W,bias,C,C16,N,K,oscale); column-blocks [N/128, N/128+N2/128) compute
// problem 2 (A2,W2,bias2,C16_2,N2,K2,oscale2). BM=BN=128, BK=64, 256 thr.
// ---------------------------------------------------------------------------
static const int HA_STRIDE = 128 * 72;   // halves per A buffer (144B rows)
static const int HW_STRIDE = 64 * 136;   // halves per W buffer (272B rows)
static const int GEMM16_SMEM = (2 * HA_STRIDE + 2 * HW_STRIDE) * 2;  // 71680 B

__global__ __launch_bounds__(256, 2) void gemm_f16_kernel(
    const __half* __restrict__ A, const __half* __restrict__ W,
    const float* __restrict__ bias, float* __restrict__ C,
    __half* __restrict__ C16, int M, int N, int K, float oscale,
    const __half* __restrict__ A2, const __half* __restrict__ W2,
    const float* __restrict__ bias2, __half* __restrict__ C16_2,
    int N2, int K2, float oscale2)
{
    extern __shared__ __half smh[];
    __half* sA = smh;                   // [2][128][72]
    __half* sW = smh + 2 * HA_STRIDE;   // [2][64][136]

    const int tid  = threadIdx.x;
    const int lane = tid & 31;
    const int warp = tid >> 5;
    const int gid  = lane >> 2;
    const int tig  = lane & 3;
    const int bm   = blockIdx.y * 128;
    const int wm   = (warp & 3) * 32;
    const int wn   = (warp >> 2) * 64;

    // select problem
    const __half* Ap; const __half* Wp; const float* bp; float* Cp; __half* C16p;
    int Np, Kp, bnl; float osc;
    if (A2 == nullptr || blockIdx.x < (unsigned)(N / 128)) {
        Ap = A;  Wp = W;  bp = bias;  Cp = C;       C16p = C16;   Np = N;  Kp = K;  osc = oscale;
        bnl = blockIdx.x * 128;
    } else {
        Ap = A2; Wp = W2; bp = bias2; Cp = nullptr; C16p = C16_2; Np = N2; Kp = K2; osc = oscale2;
        bnl = (blockIdx.x - N / 128) * 128;
    }

    float acc[2][8][4] = {};
    const int NC = Kp / 64;

    // prologue
#pragma unroll
    for (int i = 0; i < 4; i++) {
        int idx = tid + (i << 8);
        int r = idx >> 3, c = idx & 7;
        cpa16(sA + r * 72 + c * 8, Ap + (size_t)(bm + r) * Kp + c * 8);
    }
#pragma unroll
    for (int i = 0; i < 4; i++) {
        int idx = tid + (i << 8);
        int r = idx >> 4, c = idx & 15;
        cpa16(sW + r * 136 + c * 8, Wp + (size_t)r * Np + bnl + c * 8);
    }
    cp_commit();

    const unsigned shA = (unsigned)__cvta_generic_to_shared(sA);
    const unsigned shW = (unsigned)__cvta_generic_to_shared(sW);

    const int arow = lane & 15;
    const int acol = (lane >> 4) << 3;
    const int brow = (lane & 7) + (((lane >> 3) & 1) << 3);
    const int bcol = (lane >> 4) << 3;

    for (int c = 0; c < NC; ++c) {
        const int buf = c & 1;
        if (c + 1 < NC) {
            __half* dA = sA + (buf ^ 1) * HA_STRIDE;
            __half* dW = sW + (buf ^ 1) * HW_STRIDE;
            const __half* Ac = Ap + (size_t)(c + 1) * 64;
            const __half* Wc = Wp + (size_t)(c + 1) * 64 * Np;
#pragma unroll
            for (int i = 0; i < 4; i++) {
                int idx = tid + (i << 8);
                int r = idx >> 3, cc = idx & 7;
                cpa16(dA + r * 72 + cc * 8, Ac + (size_t)(bm + r) * Kp + cc * 8);
            }
#pragma unroll
            for (int i = 0; i < 4; i++) {
                int idx = tid + (i << 8);
                int r = idx >> 4, cc = idx & 15;
                cpa16(dW + r * 136 + cc * 8, Wc + (size_t)r * Np + bnl + cc * 8);
            }
            cp_commit();
            cp_wait1();
        } else {
            cp_wait0();
        }
        __syncthreads();

        const unsigned ab = shA + (unsigned)(buf * HA_STRIDE * 2);
        const unsigned wb = shW + (unsigned)(buf * HW_STRIDE * 2);

#pragma unroll
        for (int ks = 0; ks < 4; ks++) {
            unsigned af[2][4];
#pragma unroll
            for (int mt = 0; mt < 2; mt++)
                ldm_x4(af[mt][0], af[mt][1], af[mt][2], af[mt][3],
                       ab + (unsigned)(((wm + mt * 16 + arow) * 72 + ks * 16 + acol) * 2));
#pragma unroll
            for (int np = 0; np < 4; np++) {
                unsigned b0, b1, b2, b3;
                ldm_x4t(b0, b1, b2, b3,
                        wb + (unsigned)(((ks * 16 + brow) * 136 + wn + np * 16 + bcol) * 2));
                unsigned bb0[2] = {b0, b1}, bb1[2] = {b2, b3};
#pragma unroll
                for (int mt = 0; mt < 2; mt++) {
                    mma_f16(acc[mt][np * 2],     af[mt], bb0);
                    mma_f16(acc[mt][np * 2 + 1], af[mt], bb1);
                }
            }
        }
        __syncthreads();
    }

    // epilogue
#pragma unroll
    for (int mt = 0; mt < 2; mt++) {
        const int r0 = bm + wm + mt * 16 + gid;
#pragma unroll
        for (int nt = 0; nt < 8; nt++) {
            const int cc = bnl + wn + nt * 8 + 2 * tig;
            float2 bb = *(const float2*)(bp + cc);
            float2 v0, v1;
            v0.x = (acc[mt][nt][0] + bb.x) * osc; v0.y = (acc[mt][nt][1] + bb.y) * osc;
            v1.x = (acc[mt][nt][2] + bb.x) * osc; v1.y = (acc[mt][nt][3] + bb.y) * osc;
            if (Cp) {
                *(float2*)(Cp + (size_t)r0 * Np + cc) = v0;
                *(float2*)(Cp + (size_t)(r0 + 8) * Np + cc) = v1;
            }
            if (C16p) {
                *(__half2*)(C16p + (size_t)r0 * Np + cc)       = __floats2half2_rn(v0.x, v0.y);
                *(__half2*)(C16p + (size_t)(r0 + 8) * Np + cc) = __floats2half2_rn(v1.x, v1.y);
            }
        }
    }
}

// ---------------------------------------------------------------------------
// Flash attention v5: v4 + warp-uniform rescale skip (alpha==1 on tiles where
// no row-max in the warp updates -> skip Oacc/lacc rescale + 2 ex2).
// ---------------------------------------------------------------------------
static const int KPH = 72;
static const int PPH = 72;
static const int AKH = 64 * KPH;
static const int ATTN_SMEM = (4 * AKH + 8 * 16 * PPH) * 2;  // 55296 B

__global__ __launch_bounds__(256, 2) void attn_f16_kernel(
    const __half* __restrict__ Q, const __half* __restrict__ KV,
    __half* __restrict__ ctx)
{
    extern __shared__ __half smh2[];
    __half* sK = smh2;
    __half* sV = smh2 + 2 * AKH;
    __half* sP = smh2 + 4 * AKH;

    const int qb   = gridDim.x - 1 - blockIdx.x;
    const int b    = blockIdx.y >> 4;
    const int h    = blockIdx.y & 15;
    const int tid  = threadIdx.x;
    const int lane = tid & 31;
    const int warp = tid >> 5;
    const int gid  = lane >> 2;
    const int tig  = lane & 3;
    const int mb   = warp * 16;
    __half* sPw = sP + warp * 16 * PPH;

    const __half* Qb = Q  + ((size_t)b * SEQ + (size_t)qb * 128 + mb) * DIM + h * HDIM;
    const __half* Kb = KV + (size_t)b * SEQ * KVLD + h * HDIM;

#pragma unroll
    for (int i = 0; i < 4; i++) {
        int idx = tid + (i << 8);
        int kv = idx >> 9, r = (idx >> 3) & 63, c = idx & 7;
        const __half* src = Kb + (size_t)r * KVLD + c * 8 + (kv ? DIM : 0);
        __half* dst = (kv ? sV : sK) + r * KPH + c * 8;
        cpa16(dst, src);
    }
    cp_commit();

#pragma unroll
    for (int i = 0; i < 4; i++) {
        int idx = lane + (i << 5);
        int r = idx >> 3, c = idx & 7;
        *(uint4*)(sPw + r * PPH + c * 8) = *(const uint4*)(Qb + (size_t)r * DIM + c * 8);
    }
    __syncwarp();

    const unsigned shP = (unsigned)__cvta_generic_to_shared(sPw);
    const unsigned shK = (unsigned)__cvta_generic_to_shared(sK);
    const unsigned shV = (unsigned)__cvta_generic_to_shared(sV);

    const int arow = lane & 15;
    const int acol = (lane >> 4) << 3;
    const int krow = (lane & 7) + ((lane >> 4) << 3);
    const int kcol = ((lane >> 3) & 1) << 3;
    const int vrow = (lane & 7) + (((lane >> 3) & 1) << 3);
    const int vcol = (lane >> 4) << 3;

    const unsigned aoff = (unsigned)((arow * PPH + acol) * 2);
    const unsigned koff = (unsigned)((krow * KPH + kcol) * 2);
    const unsigned voff = (unsigned)((vrow * KPH + vcol) * 2);

    unsigned qf[4][4];
#pragma unroll
    for (int ks = 0; ks < 4; ks++)
        ldm_x4(qf[ks][0], qf[ks][1], qf[ks][2], qf[ks][3], shP + aoff + ks * 32);
    __syncwarp();

    const unsigned ONES2 = 0x3C003C00u;
    const unsigned onesb[2] = {ONES2, ONES2};

    float ms0 = -INFINITY, ms1 = -INFINITY;
    float Oacc[8][4] = {};
    float lacc[4] = {};
    const int jmax  = 2 * qb + 1;
    const int rg0   = qb * 128 + mb + gid;
    const int jwtop = qb * 128 + mb + 15;

    for (int j = 0; j <= jmax; ++j) {
        const int buf = j & 1;
        cp_wait0();
        __syncthreads();

        if (j < jmax) {
            __half* dK = sK + (buf ^ 1) * AKH;
            __half* dV = sV + (buf ^ 1) * AKH;
            const __half* s0 = Kb + (size_t)(j + 1) * 64 * KVLD;
#pragma unroll
            for (int i = 0; i < 4; i++) {
                int idx = tid + (i << 8);
                int kv = idx >> 9, r = (idx >> 3) & 63, c = idx & 7;
                const __half* src = s0 + (size_t)r * KVLD + c * 8 + (kv ? DIM : 0);
                __half* dst = (kv ? dV : dK) + r * KPH + c * 8;
                cpa16(dst, src);
            }
            cp_commit();
        }

        if (j * 64 > jwtop) continue;

        const unsigned kb = shK + (unsigned)(buf * AKH * 2);
        const unsigned vb = shV + (unsigned)(buf * AKH * 2);

        float sacc[8][4] = {};
#pragma unroll
        for (int ks = 0; ks < 4; ks++) {
#pragma unroll
            for (int np = 0; np < 4; np++) {
                unsigned b0, b1, b2, b3;
                ldm_x4(b0, b1, b2, b3, kb + koff + (unsigned)((np * 16 * KPH + ks * 16) * 2));
                unsigned bb0[2] = {b0, b1}, bb1[2] = {b2, b3};
                mma_f16(sacc[np * 2],     qf[ks], bb0);
                mma_f16(sacc[np * 2 + 1], qf[ks], bb1);
            }
        }

        if (j * 64 + 63 > qb * 128 + mb) {
#pragma unroll
            for (int nt = 0; nt < 8; nt++) {
                const int cg = j * 64 + nt * 8 + 2 * tig;
                if (cg     > rg0    ) sacc[nt][0] = -1e30f;
                if (cg + 1 > rg0    ) sacc[nt][1] = -1e30f;
                if (cg     > rg0 + 8) sacc[nt][2] = -1e30f;
                if (cg + 1 > rg0 + 8) sacc[nt][3] = -1e30f;
            }
        }

        float m0 = -INFINITY, m1 = -INFINITY;
#pragma unroll
        for (int nt = 0; nt < 8; nt++) {
            m0 = fmaxf(m0, fmaxf(sacc[nt][0], sacc[nt][1]));
            m1 = fmaxf(m1, fmaxf(sacc[nt][2], sacc[nt][3]));
        }
        m0 = fmaxf(m0, __shfl_xor_sync(0xffffffffu, m0, 1));
        m0 = fmaxf(m0, __shfl_xor_sync(0xffffffffu, m0, 2));
        m1 = fmaxf(m1, __shfl_xor_sync(0xffffffffu, m1, 1));
        m1 = fmaxf(m1, __shfl_xor_sync(0xffffffffu, m1, 2));
        const float mn0 = fmaxf(ms0, m0);
        const float mn1 = fmaxf(ms1, m1);

        // warp-uniform rescale skip: alpha==1 exactly when no row-max updated
        if (__any_sync(0xffffffffu, (mn0 > ms0) | (mn1 > ms1))) {
            const float a0 = ex2f(ms0 - mn0);
            const float a1 = ex2f(ms1 - mn1);
            lacc[0] *= a0; lacc[1] *= a0; lacc[2] *= a1; lacc[3] *= a1;
#pragma unroll
            for (int nt = 0; nt < 8; nt++) {
                Oacc[nt][0] *= a0; Oacc[nt][1] *= a0;
                Oacc[nt][2] *= a1; Oacc[nt][3] *= a1;
            }
            ms0 = mn0; ms1 = mn1;
        }

        __half2 mh0v = __float2half2_rn(ms0);
        __half2 mh1v = __float2half2_rn(ms1);
        unsigned mh0 = *(unsigned*)&mh0v;
        unsigned mh1 = *(unsigned*)&mh1v;

        unsigned ph[8], phb[8];
#pragma unroll
        for (int nt = 0; nt < 8; nt++) {
            ph[nt]  = ex2h2(packsub(sacc[nt][0], sacc[nt][1], mh0));
            phb[nt] = ex2h2(packsub(sacc[nt][2], sacc[nt][3], mh1));
        }

#pragma unroll
        for (int ks = 0; ks < 4; ks++) {
            unsigned pf[4] = { ph[2 * ks], phb[2 * ks], ph[2 * ks + 1], phb[2 * ks + 1] };
            mma_f16(lacc, pf, onesb);
#pragma unroll
            for (int np = 0; np < 4; np++) {
                unsigned b0, b1, b2, b3;
                ldm_x4t(b0, b1, b2, b3, vb + voff + (unsigned)((ks * 16 * KPH + np * 16) * 2));
                unsigned bb0[2] = {b0, b1}, bb1[2] = {b2, b3};
                mma_f16(Oacc[np * 2],     pf, bb0);
                mma_f16(Oacc[np * 2 + 1], pf, bb1);
            }
        }
    }

    // epilogue: normalize + write ctx (fp16)
    const float inv0 = 1.0f / lacc[0];
    const float inv1 = 1.0f / lacc[2];
    __half* cb = ctx + ((size_t)b * SEQ + (size_t)qb * 128 + mb) * DIM + h * HDIM;
#pragma unroll
    for (int nt = 0; nt < 8; nt++) {
        const int col = nt * 8 + 2 * tig;
        *(__half2*)(cb + (size_t)gid * DIM + col)       = __floats2half2_rn(Oacc[nt][0] * inv0, Oacc[nt][1] * inv0);
        *(__half2*)(cb + (size_t)(gid + 8) * DIM + col) = __floats2half2_rn(Oacc[nt][2] * inv1, Oacc[nt][3] * inv1);
    }
}

// ---------------------------------------------------------------------------
extern "C" void kernel_launch(void* const* d_in, const int* in_sizes, int n_in,
                              void* d_out, int out_size)
{
    const float* x      = (const float*)d_in[0];
    // d_in[1] = mask (tril) — causality handled analytically
    const float* w_kvc  = (const float*)d_in[2];
    const float* b_kvc  = (const float*)d_in[3];
    const float* w_kvu  = (const float*)d_in[4];
    const float* b_kvu  = (const float*)d_in[5];
    const float* w_qc   = (const float*)d_in[6];
    const float* b_qc   = (const float*)d_in[7];
    const float* w_qu   = (const float*)d_in[8];
    const float* b_qu   = (const float*)d_in[9];
    const float* w_o    = (const float*)d_in[10];
    const float* b_o    = (const float*)d_in[11];
    float* out = (float*)d_out;

    __half *x16, *kvlat16, *qlat16, *kv16, *q16, *ctx16;
    __half *wkvc16, *wkvu16, *wqc16, *wqu16, *wo16;
    cudaGetSymbolAddress((void**)&x16,     g_x16);
    cudaGetSymbolAddress((void**)&kvlat16, g_kvlat16);
    cudaGetSymbolAddress((void**)&qlat16,  g_qlat16);
    cudaGetSymbolAddress((void**)&kv16,    g_kv16);
    cudaGetSymbolAddress((void**)&q16,     g_q16);
    cudaGetSymbolAddress((void**)&ctx16,   g_ctx16);
    cudaGetSymbolAddress((void**)&wkvc16,  g_wkvc16);
    cudaGetSymbolAddress((void**)&wkvu16,  g_wkvu16);
    cudaGetSymbolAddress((void**)&wqc16,   g_wqc16);
    cudaGetSymbolAddress((void**)&wqu16,   g_wqu16);
    cudaGetSymbolAddress((void**)&wo16,    g_wo16);

    cudaFuncSetAttribute(gemm_f16_kernel, cudaFuncAttributeMaxDynamicSharedMemorySize, GEMM16_SMEM);
    cudaFuncSetAttribute(attn_f16_kernel, cudaFuncAttributeMaxDynamicSharedMemorySize, ATTN_SMEM);

    dim3 t(256);
    const float QSCALE = 0.125f * 1.44269504088896f;  // 1/sqrt(64) * log2(e)

    // (0) convert x + all 5 weight matrices to fp16
    cvt6_kernel<<<1024, 256>>>(
        x,     x16,    MTOT * DIM,
        w_kvc, wkvc16, DIM * LATENT,
        w_kvu, wkvu16, LATENT * 2 * DIM,
        w_qc,  wqc16,  DIM * QRANK,
        w_qu,  wqu16,  QRANK * DIM,
        w_o,   wo16,   DIM * DIM);

    // (1) fused: kv_latent = x@w_kvc+b_kvc  AND  q_latent = x@w_qc+b_qc
    gemm_f16_kernel<<<dim3((LATENT + QRANK) / 128, MTOT / 128), t, GEMM16_SMEM>>>(
        x16, wkvc16, b_kvc, nullptr, kvlat16, MTOT, LATENT, DIM, 1.0f,
        x16, wqc16, b_qc, qlat16, QRANK, DIM, 1.0f);

    // (2) fused: kv_up = kv_latent@w_kvu+b_kvu  AND  Q = (q_latent@w_qu+b_qu)*QSCALE
    gemm_f16_kernel<<<dim3((2 * DIM + DIM) / 128, MTOT / 128), t, GEMM16_SMEM>>>(
        kvlat16, wkvu16, b_kvu, nullptr, kv16, MTOT, 2 * DIM, LATENT, 1.0f,
        qlat16, wqu16, b_qu, q16, DIM, QRANK, QSCALE);

    // (3) attention -> ctx16
    attn_f16_kernel<<<dim3(SEQ / 128, BATCH * NHEAD), t, ATTN_SMEM>>>(q16, kv16, ctx16);

    // (4) out = ctx @ w_o + b_o  [8192,1024] fp32
    gemm_f16_kernel<<<dim3(DIM / 128, MTOT / 128), t, GEMM16_SMEM>>>(
        ctx16, wo16, b_o, out, nullptr, MTOT, DIM, DIM, 1.0f,
        nullptr, nullptr, nullptr, nullptr, 0, 0, 1.0f);
}

// round 17
// speedup vs baseline: 2.4412x; 1.0222x over previous
#include <cuda_runtime.h>
#include <cuda_fp16.h>
#include <math.h>

// Problem constants
static const int BATCH  = 4;
static const int SEQ    = 2048;
static const int DIM    = 1024;
static const int NHEAD  = 16;
static const int HDIM   = 64;
static const int LATENT = 128;
static const int QRANK  = 256;
static const int MTOT   = BATCH * SEQ;          // 8192
static const int KVLD   = 2 * DIM;              // 2048

// Scratch (no allocations allowed) ------------------------------------------
__device__ __half g_x16    [(size_t)MTOT * DIM];
__device__ __half g_kvlat16[(size_t)MTOT * LATENT];
__device__ __half g_qlat16 [(size_t)MTOT * QRANK];
__device__ __half g_kv16   [(size_t)MTOT * 2 * DIM];
__device__ __half g_q16    [(size_t)MTOT * DIM];
__device__ __half g_ctx16  [(size_t)MTOT * DIM];
__device__ __half g_wkvc16 [DIM * LATENT];
__device__ __half g_wkvu16 [LATENT * 2 * DIM];
__device__ __half g_wqc16  [DIM * QRANK];
__device__ __half g_wqu16  [QRANK * DIM];
__device__ __half g_wo16   [DIM * DIM];

// ---------------------------------------------------------------------------
// helpers
// ---------------------------------------------------------------------------
__device__ __forceinline__ void mma_f16(float* d, const unsigned* a, const unsigned* b) {
    asm volatile(
        "mma.sync.aligned.m16n8k16.row.col.f32.f16.f16.f32 "
        "{%0,%1,%2,%3}, {%4,%5,%6,%7}, {%8,%9}, {%0,%1,%2,%3};"
        : "+f"(d[0]), "+f"(d[1]), "+f"(d[2]), "+f"(d[3])
        : "r"(a[0]), "r"(a[1]), "r"(a[2]), "r"(a[3]), "r"(b[0]), "r"(b[1]));
}

__device__ __forceinline__ void ldm_x4(unsigned& r0, unsigned& r1, unsigned& r2, unsigned& r3,
                                       unsigned addr) {
    asm volatile("ldmatrix.sync.aligned.m8n8.x4.shared.b16 {%0,%1,%2,%3}, [%4];"
        : "=r"(r0), "=r"(r1), "=r"(r2), "=r"(r3) : "r"(addr));
}
__device__ __forceinline__ void ldm_x4t(unsigned& r0, unsigned& r1, unsigned& r2, unsigned& r3,
                                        unsigned addr) {
    asm volatile("ldmatrix.sync.aligned.m8n8.x4.trans.shared.b16 {%0,%1,%2,%3}, [%4];"
        : "=r"(r0), "=r"(r1), "=r"(r2), "=r"(r3) : "r"(addr));
}

__device__ __forceinline__ float ex2f(float x) {
    float y;
    asm("ex2.approx.f32 %0, %1;" : "=f"(y) : "f"(x));
    return y;
}
__device__ __forceinline__ unsigned ex2h2(unsigned x) {
    unsigned y;
    asm("ex2.approx.f16x2 %0, %1;" : "=r"(y) : "r"(x));
    return y;
}
__device__ __forceinline__ unsigned packsub(float a, float b, unsigned mh2) {
    __half2 v = __floats2half2_rn(a, b);
    unsigned vu = *(unsigned*)&v;
    __half2 m = *(__half2*)&mh2;
    __half2 r = __hsub2(*(__half2*)&vu, m);
    return *(unsigned*)&r;
}

__device__ __forceinline__ void cpa16(void* smem, const void* g) {
    unsigned s = (unsigned)__cvta_generic_to_shared(smem);
    asm volatile("cp.async.cg.shared.global [%0], [%1], 16;" :: "r"(s), "l"(g));
}
__device__ __forceinline__ void cp_commit() { asm volatile("cp.async.commit_group;"); }
__device__ __forceinline__ void cp_wait1()  { asm volatile("cp.async.wait_group 1;"); }
__device__ __forceinline__ void cp_wait0()  { asm volatile("cp.async.wait_group 0;"); }

// ---------------------------------------------------------------------------
// cvt: fp32 -> fp16 for x and the 5 weight matrices (one launch)
// ---------------------------------------------------------------------------
__global__ void cvt6_kernel(
    const float* s0, __half* d0, int n0, const float* s1, __half* d1, int n1,
    const float* s2, __half* d2, int n2, const float* s3, __half* d3, int n3,
    const float* s4, __half* d4, int n4, const float* s5, __half* d5, int n5)
{
    const int t = blockIdx.x * blockDim.x + threadIdx.x;
    const int stride = gridDim.x * blockDim.x;
#define CV6(s, d, n) \
    for (int i = t; i < (n) / 2; i += stride) { \
        float2 v = ((const float2*)(s))[i]; \
        ((__half2*)(d))[i] = __floats2half2_rn(v.x, v.y); \
    }
    CV6(s0, d0, n0); CV6(s1, d1, n1); CV6(s2, d2, n2);
    CV6(s3, d3, n3); CV6(s4, d4, n4); CV6(s5, d5, n5);
#undef CV6
}

// ---------------------------------------------------------------------------
// fp16 GEMM, dual-problem (unchanged)
// ---------------------------------------------------------------------------
static const int HA_STRIDE = 128 * 72;
static const int HW_STRIDE = 64 * 136;
static const int GEMM16_SMEM = (2 * HA_STRIDE + 2 * HW_STRIDE) * 2;  // 71680 B

__global__ __launch_bounds__(256, 2) void gemm_f16_kernel(
    const __half* __restrict__ A, const __half* __restrict__ W,
    const float* __restrict__ bias, float* __restrict__ C,
    __half* __restrict__ C16, int M, int N, int K, float oscale,
    const __half* __restrict__ A2, const __half* __restrict__ W2,
    const float* __restrict__ bias2, __half* __restrict__ C16_2,
    int N2, int K2, float oscale2)
{
    extern __shared__ __half smh[];
    __half* sA = smh;
    __half* sW = smh + 2 * HA_STRIDE;

    const int tid  = threadIdx.x;
    const int lane = tid & 31;
    const int warp = tid >> 5;
    const int gid  = lane >> 2;
    const int tig  = lane & 3;
    const int bm   = blockIdx.y * 128;
    const int wm   = (warp & 3) * 32;
    const int wn   = (warp >> 2) * 64;

    const __half* Ap; const __half* Wp; const float* bp; float* Cp; __half* C16p;
    int Np, Kp, bnl; float osc;
    if (A2 == nullptr || blockIdx.x < (unsigned)(N / 128)) {
        Ap = A;  Wp = W;  bp = bias;  Cp = C;       C16p = C16;   Np = N;  Kp = K;  osc = oscale;
        bnl = blockIdx.x * 128;
    } else {
        Ap = A2; Wp = W2; bp = bias2; Cp = nullptr; C16p = C16_2; Np = N2; Kp = K2; osc = oscale2;
        bnl = (blockIdx.x - N / 128) * 128;
    }

    float acc[2][8][4] = {};
    const int NC = Kp / 64;

#pragma unroll
    for (int i = 0; i < 4; i++) {
        int idx = tid + (i << 8);
        int r = idx >> 3, c = idx & 7;
        cpa16(sA + r * 72 + c * 8, Ap + (size_t)(bm + r) * Kp + c * 8);
    }
#pragma unroll
    for (int i = 0; i < 4; i++) {
        int idx = tid + (i << 8);
        int r = idx >> 4, c = idx & 15;
        cpa16(sW + r * 136 + c * 8, Wp + (size_t)r * Np + bnl + c * 8);
    }
    cp_commit();

    const unsigned shA = (unsigned)__cvta_generic_to_shared(sA);
    const unsigned shW = (unsigned)__cvta_generic_to_shared(sW);

    const int arow = lane & 15;
    const int acol = (lane >> 4) << 3;
    const int brow = (lane & 7) + (((lane >> 3) & 1) << 3);
    const int bcol = (lane >> 4) << 3;

    for (int c = 0; c < NC; ++c) {
        const int buf = c & 1;
        if (c + 1 < NC) {
            __half* dA = sA + (buf ^ 1) * HA_STRIDE;
            __half* dW = sW + (buf ^ 1) * HW_STRIDE;
            const __half* Ac = Ap + (size_t)(c + 1) * 64;
            const __half* Wc = Wp + (size_t)(c + 1) * 64 * Np;
#pragma unroll
            for (int i = 0; i < 4; i++) {
                int idx = tid + (i << 8);
                int r = idx >> 3, cc = idx & 7;
                cpa16(dA + r * 72 + cc * 8, Ac + (size_t)(bm + r) * Kp + cc * 8);
            }
#pragma unroll
            for (int i = 0; i < 4; i++) {
                int idx = tid + (i << 8);
                int r = idx >> 4, cc = idx & 15;
                cpa16(dW + r * 136 + cc * 8, Wc + (size_t)r * Np + bnl + cc * 8);
            }
            cp_commit();
            cp_wait1();
        } else {
            cp_wait0();
        }
        __syncthreads();

        const unsigned ab = shA + (unsigned)(buf * HA_STRIDE * 2);
        const unsigned wb = shW + (unsigned)(buf * HW_STRIDE * 2);

#pragma unroll
        for (int ks = 0; ks < 4; ks++) {
            unsigned af[2][4];
#pragma unroll
            for (int mt = 0; mt < 2; mt++)
                ldm_x4(af[mt][0], af[mt][1], af[mt][2], af[mt][3],
                       ab + (unsigned)(((wm + mt * 16 + arow) * 72 + ks * 16 + acol) * 2));
#pragma unroll
            for (int np = 0; np < 4; np++) {
                unsigned b0, b1, b2, b3;
                ldm_x4t(b0, b1, b2, b3,
                        wb + (unsigned)(((ks * 16 + brow) * 136 + wn + np * 16 + bcol) * 2));
                unsigned bb0[2] = {b0, b1}, bb1[2] = {b2, b3};
#pragma unroll
                for (int mt = 0; mt < 2; mt++) {
                    mma_f16(acc[mt][np * 2],     af[mt], bb0);
                    mma_f16(acc[mt][np * 2 + 1], af[mt], bb1);
                }
            }
        }
        __syncthreads();
    }

#pragma unroll
    for (int mt = 0; mt < 2; mt++) {
        const int r0 = bm + wm + mt * 16 + gid;
#pragma unroll
        for (int nt = 0; nt < 8; nt++) {
            const int cc = bnl + wn + nt * 8 + 2 * tig;
            float2 bb = *(const float2*)(bp + cc);
            float2 v0, v1;
            v0.x = (acc[mt][nt][0] + bb.x) * osc; v0.y = (acc[mt][nt][1] + bb.y) * osc;
            v1.x = (acc[mt][nt][2] + bb.x) * osc; v1.y = (acc[mt][nt][3] + bb.y) * osc;
            if (Cp) {
                *(float2*)(Cp + (size_t)r0 * Np + cc) = v0;
                *(float2*)(Cp + (size_t)(r0 + 8) * Np + cc) = v1;
            }
            if (C16p) {
                *(__half2*)(C16p + (size_t)r0 * Np + cc)       = __floats2half2_rn(v0.x, v0.y);
                *(__half2*)(C16p + (size_t)(r0 + 8) * Np + cc) = __floats2half2_rn(v1.x, v1.y);
            }
        }
    }
}

// ---------------------------------------------------------------------------
// Flash attention v6: 4 warps x 32 q-rows (two 16-row bands per warp).
// Each K/V B-fragment feeds TWO mma per band pair -> ldmatrix traffic halved.
// 128 threads/block, 128 q-rows/block, grid unchanged.
// ---------------------------------------------------------------------------
static const int KPH = 72;
static const int PPH = 72;
static const int AKH = 64 * KPH;
static const int ATTN_SMEM = (4 * AKH + 4 * 32 * PPH) * 2;  // 55296 B

__global__ __launch_bounds__(128, 2) void attn_f16_kernel(
    const __half* __restrict__ Q, const __half* __restrict__ KV,
    __half* __restrict__ ctx)
{
    extern __shared__ __half smh2[];
    __half* sK = smh2;
    __half* sV = smh2 + 2 * AKH;
    __half* sP = smh2 + 4 * AKH;

    const int qb   = gridDim.x - 1 - blockIdx.x;
    const int b    = blockIdx.y >> 4;
    const int h    = blockIdx.y & 15;
    const int tid  = threadIdx.x;
    const int lane = tid & 31;
    const int warp = tid >> 5;          // 0..3
    const int gid  = lane >> 2;
    const int tig  = lane & 3;
    const int mb   = warp * 32;         // warp's 32 q rows
    __half* sPw = sP + warp * 32 * PPH;

    const __half* Qb = Q  + ((size_t)b * SEQ + (size_t)qb * 128 + mb) * DIM + h * HDIM;
    const __half* Kb = KV + (size_t)b * SEQ * KVLD + h * HDIM;

    // prologue: prefetch K/V tile 0 (1024 16B chunks, 128 threads -> 8 each)
#pragma unroll
    for (int i = 0; i < 8; i++) {
        int idx = tid + (i << 7);
        int kv = idx >> 9, r = (idx >> 3) & 63, c = idx & 7;
        const __half* src = Kb + (size_t)r * KVLD + c * 8 + (kv ? DIM : 0);
        __half* dst = (kv ? sV : sK) + r * KPH + c * 8;
        cpa16(dst, src);
    }
    cp_commit();

    // stage this warp's Q (32 rows x 64 halves)
#pragma unroll
    for (int i = 0; i < 8; i++) {
        int idx = lane + (i << 5);       // 0..255
        int r = idx >> 3, c = idx & 7;
        *(uint4*)(sPw + r * PPH + c * 8) = *(const uint4*)(Qb + (size_t)r * DIM + c * 8);
    }
    __syncwarp();

    const unsigned shP = (unsigned)__cvta_generic_to_shared(sPw);
    const unsigned shK = (unsigned)__cvta_generic_to_shared(sK);
    const unsigned shV = (unsigned)__cvta_generic_to_shared(sV);

    const int arow = lane & 15;
    const int acol = (lane >> 4) << 3;
    const int krow = (lane & 7) + ((lane >> 4) << 3);
    const int kcol = ((lane >> 3) & 1) << 3;
    const int vrow = (lane & 7) + (((lane >> 3) & 1) << 3);
    const int vcol = (lane >> 4) << 3;

    const unsigned koff = (unsigned)((krow * KPH + kcol) * 2);
    const unsigned voff = (unsigned)((vrow * KPH + vcol) * 2);

    // Q fragments for both bands (registers, whole kernel): 32 regs
    unsigned qf[2][4][4];
#pragma unroll
    for (int bd = 0; bd < 2; bd++) {
        const unsigned ao = (unsigned)(((bd * 16 + arow) * PPH + acol) * 2);
#pragma unroll
        for (int ks = 0; ks < 4; ks++)
            ldm_x4(qf[bd][ks][0], qf[bd][ks][1], qf[bd][ks][2], qf[bd][ks][3],
                   shP + ao + ks * 32);
    }
    __syncwarp();

    const unsigned ONES2 = 0x3C003C00u;
    const unsigned onesb[2] = {ONES2, ONES2};

    float ms_a = -INFINITY, ms_b = -INFINITY, ms_c = -INFINITY, ms_d = -INFINITY;
    float O0[8][4] = {}, O1[8][4] = {};
    float l0[4] = {}, l1[4] = {};
    const int jmax  = 2 * qb + 1;
    const int rgA   = qb * 128 + mb + gid;        // band0 rows: rgA, rgA+8
    const int rgC   = rgA + 16;                   // band1 rows: rgC, rgC+8
    const int jwtop = qb * 128 + mb + 31;

    for (int j = 0; j <= jmax; ++j) {
        const int buf = j & 1;
        cp_wait0();
        __syncthreads();

        if (j < jmax) {
            __half* dK = sK + (buf ^ 1) * AKH;
            __half* dV = sV + (buf ^ 1) * AKH;
            const __half* s0g = Kb + (size_t)(j + 1) * 64 * KVLD;
#pragma unroll
            for (int i = 0; i < 8; i++) {
                int idx = tid + (i << 7);
                int kv = idx >> 9, r = (idx >> 3) & 63, c = idx & 7;
                const __half* src = s0g + (size_t)r * KVLD + c * 8 + (kv ? DIM : 0);
                __half* dst = (kv ? dV : dK) + r * KPH + c * 8;
                cpa16(dst, src);
            }
            cp_commit();
        }

        if (j * 64 > jwtop) continue;

        const unsigned kb = shK + (unsigned)(buf * AKH * 2);
        const unsigned vb = shV + (unsigned)(buf * AKH * 2);

        // S = Q @ K^T for BOTH bands; each K fragment feeds 4 mma
        float s0[8][4] = {}, s1[8][4] = {};
#pragma unroll
        for (int ks = 0; ks < 4; ks++) {
#pragma unroll
            for (int np = 0; np < 4; np++) {
                unsigned b0, b1, b2, b3;
                ldm_x4(b0, b1, b2, b3, kb + koff + (unsigned)((np * 16 * KPH + ks * 16) * 2));
                unsigned bb0[2] = {b0, b1}, bb1[2] = {b2, b3};
                mma_f16(s0[np * 2],     qf[0][ks], bb0);
                mma_f16(s0[np * 2 + 1], qf[0][ks], bb1);
                mma_f16(s1[np * 2],     qf[1][ks], bb0);
                mma_f16(s1[np * 2 + 1], qf[1][ks], bb1);
            }
        }

        // causal mask (diagonal tiles only)
        if (j * 64 + 63 > qb * 128 + mb) {
#pragma unroll
            for (int nt = 0; nt < 8; nt++) {
                const int cg = j * 64 + nt * 8 + 2 * tig;
                if (cg     > rgA    ) s0[nt][0] = -1e30f;
                if (cg + 1 > rgA    ) s0[nt][1] = -1e30f;
                if (cg     > rgA + 8) s0[nt][2] = -1e30f;
                if (cg + 1 > rgA + 8) s0[nt][3] = -1e30f;
                if (cg     > rgC    ) s1[nt][0] = -1e30f;
                if (cg + 1 > rgC    ) s1[nt][1] = -1e30f;
                if (cg     > rgC + 8) s1[nt][2] = -1e30f;
                if (cg + 1 > rgC + 8) s1[nt][3] = -1e30f;
            }
        }

        // row maxima (4 row-states)
        float m_a = -INFINITY, m_b = -INFINITY, m_c = -INFINITY, m_d = -INFINITY;
#pragma unroll
        for (int nt = 0; nt < 8; nt++) {
            m_a = fmaxf(m_a, fmaxf(s0[nt][0], s0[nt][1]));
            m_b = fmaxf(m_b, fmaxf(s0[nt][2], s0[nt][3]));
            m_c = fmaxf(m_c, fmaxf(s1[nt][0], s1[nt][1]));
            m_d = fmaxf(m_d, fmaxf(s1[nt][2], s1[nt][3]));
        }
        m_a = fmaxf(m_a, __shfl_xor_sync(0xffffffffu, m_a, 1));
        m_a = fmaxf(m_a, __shfl_xor_sync(0xffffffffu, m_a, 2));
        m_b = fmaxf(m_b, __shfl_xor_sync(0xffffffffu, m_b, 1));
        m_b = fmaxf(m_b, __shfl_xor_sync(0xffffffffu, m_b, 2));
        m_c = fmaxf(m_c, __shfl_xor_sync(0xffffffffu, m_c, 1));
        m_c = fmaxf(m_c, __shfl_xor_sync(0xffffffffu, m_c, 2));
        m_d = fmaxf(m_d, __shfl_xor_sync(0xffffffffu, m_d, 1));
        m_d = fmaxf(m_d, __shfl_xor_sync(0xffffffffu, m_d, 2));
        const float n_a = fmaxf(ms_a, m_a), n_b = fmaxf(ms_b, m_b);
        const float n_c = fmaxf(ms_c, m_c), n_d = fmaxf(ms_d, m_d);

        if (__any_sync(0xffffffffu,
                       (n_a > ms_a) | (n_b > ms_b) | (n_c > ms_c) | (n_d > ms_d))) {
            const float a0 = ex2f(ms_a - n_a);
            const float a1 = ex2f(ms_b - n_b);
            const float a2 = ex2f(ms_c - n_c);
            const float a3 = ex2f(ms_d - n_d);
            l0[0] *= a0; l0[1] *= a0; l0[2] *= a1; l0[3] *= a1;
            l1[0] *= a2; l1[1] *= a2; l1[2] *= a3; l1[3] *= a3;
#pragma unroll
            for (int nt = 0; nt < 8; nt++) {
                O0[nt][0] *= a0; O0[nt][1] *= a0; O0[nt][2] *= a1; O0[nt][3] *= a1;
                O1[nt][0] *= a2; O1[nt][1] *= a2; O1[nt][2] *= a3; O1[nt][3] *= a3;
            }
            ms_a = n_a; ms_b = n_b; ms_c = n_c; ms_d = n_d;
        }

        __half2 ha = __float2half2_rn(ms_a), hb = __float2half2_rn(ms_b);
        __half2 hc = __float2half2_rn(ms_c), hd = __float2half2_rn(ms_d);
        unsigned mha = *(unsigned*)&ha, mhb = *(unsigned*)&hb;
        unsigned mhc = *(unsigned*)&hc, mhd = *(unsigned*)&hd;

        unsigned p0[8], p0b[8], p1[8], p1b[8];
#pragma unroll
        for (int nt = 0; nt < 8; nt++) {
            p0[nt]  = ex2h2(packsub(s0[nt][0], s0[nt][1], mha));
            p0b[nt] = ex2h2(packsub(s0[nt][2], s0[nt][3], mhb));
            p1[nt]  = ex2h2(packsub(s1[nt][0], s1[nt][1], mhc));
            p1b[nt] = ex2h2(packsub(s1[nt][2], s1[nt][3], mhd));
        }

        // O += P @ V for BOTH bands; each V fragment feeds 4 mma. l via ones-mma.
#pragma unroll
        for (int ks = 0; ks < 4; ks++) {
            unsigned pf0[4] = { p0[2 * ks], p0b[2 * ks], p0[2 * ks + 1], p0b[2 * ks + 1] };
            unsigned pf1[4] = { p1[2 * ks], p1b[2 * ks], p1[2 * ks + 1], p1b[2 * ks + 1] };
            mma_f16(l0, pf0, onesb);
            mma_f16(l1, pf1, onesb);
#pragma unroll
            for (int np = 0; np < 4; np++) {
                unsigned b0, b1, b2, b3;
                ldm_x4t(b0, b1, b2, b3, vb + voff + (unsigned)((ks * 16 * KPH + np * 16) * 2));
                unsigned bb0[2] = {b0, b1}, bb1[2] = {b2, b3};
                mma_f16(O0[np * 2],     pf0, bb0);
                mma_f16(O0[np * 2 + 1], pf0, bb1);
                mma_f16(O1[np * 2],     pf1, bb0);
                mma_f16(O1[np * 2 + 1], pf1, bb1);
            }
        }
    }

    // epilogue: normalize + write ctx (fp16), 32 rows
    const float iA = 1.0f / l0[0];
    const float iB = 1.0f / l0[2];
    const float iC = 1.0f / l1[0];
    const float iD = 1.0f / l1[2];
    __half* cb = ctx + ((size_t)b * SEQ + (size_t)qb * 128 + mb) * DIM + h * HDIM;
#pragma unroll
    for (int nt = 0; nt < 8; nt++) {
        const int col = nt * 8 + 2 * tig;
        *(__half2*)(cb + (size_t)gid * DIM + col)        = __floats2half2_rn(O0[nt][0] * iA, O0[nt][1] * iA);
        *(__half2*)(cb + (size_t)(gid + 8) * DIM + col)  = __floats2half2_rn(O0[nt][2] * iB, O0[nt][3] * iB);
        *(__half2*)(cb + (size_t)(gid + 16) * DIM + col) = __floats2half2_rn(O1[nt][0] * iC, O1[nt][1] * iC);
        *(__half2*)(cb + (size_t)(gid + 24) * DIM + col) = __floats2half2_rn(O1[nt][2] * iD, O1[nt][3] * iD);
    }
}

// ---------------------------------------------------------------------------
extern "C" void kernel_launch(void* const* d_in, const int* in_sizes, int n_in,
                              void* d_out, int out_size)
{
    const float* x      = (const float*)d_in[0];
    // d_in[1] = mask (tril) — causality handled analytically
    const float* w_kvc  = (const float*)d_in[2];
    const float* b_kvc  = (const float*)d_in[3];
    const float* w_kvu  = (const float*)d_in[4];
    const float* b_kvu  = (const float*)d_in[5];
    const float* w_qc   = (const float*)d_in[6];
    const float* b_qc   = (const float*)d_in[7];
    const float* w_qu   = (const float*)d_in[8];
    const float* b_qu   = (const float*)d_in[9];
    const float* w_o    = (const float*)d_in[10];
    const float* b_o    = (const float*)d_in[11];
    float* out = (float*)d_out;

    __half *x16, *kvlat16, *qlat16, *kv16, *q16, *ctx16;
    __half *wkvc16, *wkvu16, *wqc16, *wqu16, *wo16;
    cudaGetSymbolAddress((void**)&x16,     g_x16);
    cudaGetSymbolAddress((void**)&kvlat16, g_kvlat16);
    cudaGetSymbolAddress((void**)&qlat16,  g_qlat16);
    cudaGetSymbolAddress((void**)&kv16,    g_kv16);
    cudaGetSymbolAddress((void**)&q16,     g_q16);
    cudaGetSymbolAddress((void**)&ctx16,   g_ctx16);
    cudaGetSymbolAddress((void**)&wkvc16,  g_wkvc16);
    cudaGetSymbolAddress((void**)&wkvu16,  g_wkvu16);
    cudaGetSymbolAddress((void**)&wqc16,   g_wqc16);
    cudaGetSymbolAddress((void**)&wqu16,   g_wqu16);
    cudaGetSymbolAddress((void**)&wo16,    g_wo16);

    cudaFuncSetAttribute(gemm_f16_kernel, cudaFuncAttributeMaxDynamicSharedMemorySize, GEMM16_SMEM);
    cudaFuncSetAttribute(attn_f16_kernel, cudaFuncAttributeMaxDynamicSharedMemorySize, ATTN_SMEM);

    dim3 t(256);
    const float QSCALE = 0.125f * 1.44269504088896f;  // 1/sqrt(64) * log2(e)

    // (0) convert x + all 5 weight matrices to fp16
    cvt6_kernel<<<1024, 256>>>(
        x,     x16,    MTOT * DIM,
        w_kvc, wkvc16, DIM * LATENT,
        w_kvu, wkvu16, LATENT * 2 * DIM,
        w_qc,  wqc16,  DIM * QRANK,
        w_qu,  wqu16,  QRANK * DIM,
        w_o,   wo16,   DIM * DIM);

    // (1) fused: kv_latent = x@w_kvc+b_kvc  AND  q_latent = x@w_qc+b_qc
    gemm_f16_kernel<<<dim3((LATENT + QRANK) / 128, MTOT / 128), t, GEMM16_SMEM>>>(
        x16, wkvc16, b_kvc, nullptr, kvlat16, MTOT, LATENT, DIM, 1.0f,
        x16, wqc16, b_qc, qlat16, QRANK, DIM, 1.0f);

    // (2) fused: kv_up = kv_latent@w_kvu+b_kvu  AND  Q = (q_latent@w_qu+b_qu)*QSCALE
    gemm_f16_kernel<<<dim3((2 * DIM + DIM) / 128, MTOT / 128), t, GEMM16_SMEM>>>(
        kvlat16, wkvu16, b_kvu, nullptr, kv16, MTOT, 2 * DIM, LATENT, 1.0f,
        qlat16, wqu16, b_qu, q16, DIM, QRANK, QSCALE);

    // (3) attention -> ctx16  (128 threads: 4 warps x 32 rows)
    attn_f16_kernel<<<dim3(SEQ / 128, BATCH * NHEAD), dim3(128), ATTN_SMEM>>>(q16, kv16, ctx16);

    // (4) out = ctx @ w_o + b_o  [8192,1024] fp32
    gemm_f16_kernel<<<dim3(DIM / 128, MTOT / 128), t, GEMM16_SMEM>>>(
        ctx16, wo16, b_o, out, nullptr, MTOT, DIM, DIM, 1.0f,
        nullptr, nullptr, nullptr, nullptr, 0, 0, 1.0f);
}